// round 2
// baseline (speedup 1.0000x reference)
#include <cuda_runtime.h>

// ---------------- problem constants ----------------
#define BATCH   1024
#define NSAMP   8
#define KDIM    6
#define NITERS  20

// conv shapes
// conv1: [B,3,64,64] -> [B,32,30,30]
// conv2: [B,32,30,30] -> [B,64,13,13]
// conv3: [B,64,13,13] -> [B,128,5,5]
// conv4: [B,128,5,5]  -> [B,256]  (GEMM 1024x256x3200)

// ---------------- scratch (device globals; no allocs allowed) ----------------
__device__ float g_act1[BATCH * 32 * 30 * 30];   // 118 MB
__device__ float g_act2[BATCH * 64 * 13 * 13];   // 44 MB
__device__ float g_act3[BATCH * 128 * 5 * 5];    // 13 MB
__device__ float g_feat[BATCH * 256];
__device__ float g_logalpha[BATCH * 36];

// ============================================================================
// conv1: grid (1024, 4), block 256.  blockIdx.y selects 8 output channels.
// Each thread: 4 spatial positions x 8 oc accumulators.
// ============================================================================
__global__ __launch_bounds__(256) void conv1_kernel(
    const float* __restrict__ im, const float* __restrict__ w1,
    const float* __restrict__ b1)
{
    __shared__ float s_in[64 * 64];   // one input channel plane
    __shared__ float s_w[8 * 75];     // 8 oc x (3*25) weights

    const int b   = blockIdx.x;
    const int oc0 = blockIdx.y * 8;
    const int t   = threadIdx.x;

    // weights for this oc group are contiguous in w1
    for (int i = t; i < 600; i += 256) s_w[i] = w1[oc0 * 75 + i];

    float acc[4][8];
#pragma unroll
    for (int i = 0; i < 4; i++)
#pragma unroll
        for (int o = 0; o < 8; o++) acc[i][o] = 0.f;

    int bo[4];
    bool val[4];
#pragma unroll
    for (int i = 0; i < 4; i++) {
        int p = t + 256 * i;
        val[i] = (p < 900);
        int oy = p / 30, ox = p % 30;
        bo[i] = val[i] ? (2 * oy * 64 + 2 * ox) : 0;
    }

#pragma unroll 1
    for (int c = 0; c < 3; c++) {
        __syncthreads();
        const float4* src = reinterpret_cast<const float4*>(im + (b * 3 + c) * 4096);
        float4* dst = reinterpret_cast<float4*>(s_in);
        for (int e = t; e < 1024; e += 256) dst[e] = src[e];
        __syncthreads();

#pragma unroll
        for (int ky = 0; ky < 5; ky++) {
#pragma unroll
            for (int kx = 0; kx < 5; kx++) {
                float w8[8];
#pragma unroll
                for (int o = 0; o < 8; o++)
                    w8[o] = s_w[o * 75 + c * 25 + ky * 5 + kx];
#pragma unroll
                for (int i = 0; i < 4; i++) {
                    float v = s_in[bo[i] + ky * 64 + kx];
#pragma unroll
                    for (int o = 0; o < 8; o++) acc[i][o] += v * w8[o];
                }
            }
        }
    }

#pragma unroll
    for (int o = 0; o < 8; o++) {
        float bias = b1[oc0 + o];
#pragma unroll
        for (int i = 0; i < 4; i++) {
            int p = t + 256 * i;
            if (val[i])
                g_act1[(b * 32 + oc0 + o) * 900 + p] = fmaxf(acc[i][o] + bias, 0.f);
        }
    }
}

// ============================================================================
// conv2: grid 1024, block 352.  t -> (g = t/44 oc-group of 8, p0 = t%44),
// each thread 4 spatial positions (p0 + 44*i) x 8 oc.
// ============================================================================
__global__ __launch_bounds__(352) void conv2_kernel(
    const float* __restrict__ w2, const float* __restrict__ b2)
{
    __shared__ float s_in[30 * 30];   // one input channel plane
    __shared__ float s_w[64 * 25];    // all 64 oc weights for current c

    const int b  = blockIdx.x;
    const int t  = threadIdx.x;
    const int g  = t / 44;            // 0..7
    const int p0 = t % 44;

    float acc[4][8];
#pragma unroll
    for (int i = 0; i < 4; i++)
#pragma unroll
        for (int o = 0; o < 8; o++) acc[i][o] = 0.f;

    int bo[4];
    bool val[4];
#pragma unroll
    for (int i = 0; i < 4; i++) {
        int p = p0 + 44 * i;
        val[i] = (p < 169);
        int oy = p / 13, ox = p % 13;
        bo[i] = val[i] ? (2 * oy * 30 + 2 * ox) : 0;
    }

#pragma unroll 1
    for (int c = 0; c < 32; c++) {
        __syncthreads();
        {
            const float4* src = reinterpret_cast<const float4*>(g_act1 + (b * 32 + c) * 900);
            float4* dst = reinterpret_cast<float4*>(s_in);
            for (int e = t; e < 225; e += 352) dst[e] = src[e];
        }
        for (int i = t; i < 1600; i += 352) {
            int oc = i / 25, j = i % 25;
            s_w[i] = w2[oc * 800 + c * 25 + j];
        }
        __syncthreads();

#pragma unroll 1
        for (int ky = 0; ky < 5; ky++) {
#pragma unroll
            for (int kx = 0; kx < 5; kx++) {
                float w8[8];
#pragma unroll
                for (int o = 0; o < 8; o++)
                    w8[o] = s_w[(g * 8 + o) * 25 + ky * 5 + kx];
#pragma unroll
                for (int i = 0; i < 4; i++) {
                    float v = s_in[bo[i] + ky * 30 + kx];
#pragma unroll
                    for (int o = 0; o < 8; o++) acc[i][o] += v * w8[o];
                }
            }
        }
    }

#pragma unroll
    for (int o = 0; o < 8; o++) {
        int oc = g * 8 + o;
        float bias = b2[oc];
#pragma unroll
        for (int i = 0; i < 4; i++) {
            int p = p0 + 44 * i;
            if (val[i])
                g_act2[(b * 64 + oc) * 169 + p] = fmaxf(acc[i][o] + bias, 0.f);
        }
    }
}

// ============================================================================
// conv3: grid 1024, block 128 (t = oc). Input staged in smem in chunks of 16
// channels; input rows register-cached; weights per-(oc,c) loaded to regs.
// ============================================================================
__global__ __launch_bounds__(128) void conv3_kernel(
    const float* __restrict__ w3, const float* __restrict__ b3)
{
    __shared__ float s_in[16 * 169];

    const int b = blockIdx.x;
    const int t = threadIdx.x;   // oc

    float acc[25];
#pragma unroll
    for (int s = 0; s < 25; s++) acc[s] = 0.f;

#pragma unroll 1
    for (int cc = 0; cc < 4; cc++) {
        __syncthreads();
        const float* src = g_act2 + (b * 64 + cc * 16) * 169;
        for (int i = t; i < 2704; i += 128) s_in[i] = src[i];
        __syncthreads();

#pragma unroll 1
        for (int c16 = 0; c16 < 16; c16++) {
            int c = cc * 16 + c16;
            float wr[25];
#pragma unroll
            for (int j = 0; j < 25; j++)
                wr[j] = w3[t * 1600 + c * 25 + j];
            const float* sp = s_in + c16 * 169;

#pragma unroll
            for (int r = 0; r < 13; r++) {
                float row[13];
#pragma unroll
                for (int x = 0; x < 13; x++) row[x] = sp[r * 13 + x];
#pragma unroll
                for (int oy = 0; oy < 5; oy++) {
                    int ky = r - 2 * oy;
                    if (ky >= 0 && ky < 5) {
#pragma unroll
                        for (int kx = 0; kx < 5; kx++) {
                            float wv = wr[ky * 5 + kx];
#pragma unroll
                            for (int ox = 0; ox < 5; ox++)
                                acc[oy * 5 + ox] += wv * row[2 * ox + kx];
                        }
                    }
                }
            }
        }
    }

    float bias = b3[t];
#pragma unroll
    for (int s = 0; s < 25; s++)
        g_act3[(b * 128 + t) * 25 + s] = fmaxf(acc[s] + bias, 0.f);
}

// ============================================================================
// conv4 as GEMM: C[1024,256] = A[1024,3200] @ W^T.  BM=64, BN=32, BK=32.
// grid (16, 8), block 256; thread computes 2x4 outputs.
// ============================================================================
__global__ __launch_bounds__(256) void conv4_kernel(
    const float* __restrict__ w4, const float* __restrict__ b4)
{
    __shared__ float s_a[32 * 65];
    __shared__ float s_w[32 * 33];

    const int bm = blockIdx.x * 64;
    const int bn = blockIdx.y * 32;
    const int t  = threadIdx.x;
    const int tx = t & 7;    // col group (4 cols)
    const int ty = t >> 3;   // row group (2 rows)

    const float* A = g_act3;  // [1024][3200]

    float acc[2][4];
#pragma unroll
    for (int i = 0; i < 2; i++)
#pragma unroll
        for (int j = 0; j < 4; j++) acc[i][j] = 0.f;

#pragma unroll 1
    for (int k0 = 0; k0 < 3200; k0 += 32) {
        __syncthreads();
        for (int e = t; e < 2048; e += 256) {
            int r = e >> 5, kk = e & 31;
            s_a[kk * 65 + r] = A[(bm + r) * 3200 + k0 + kk];
        }
        for (int e = t; e < 1024; e += 256) {
            int r = e >> 5, kk = e & 31;
            s_w[kk * 33 + r] = w4[(bn + r) * 3200 + k0 + kk];
        }
        __syncthreads();

#pragma unroll 8
        for (int kk = 0; kk < 32; kk++) {
            float a0 = s_a[kk * 65 + ty * 2 + 0];
            float a1 = s_a[kk * 65 + ty * 2 + 1];
            float w0 = s_w[kk * 33 + tx * 4 + 0];
            float w1_ = s_w[kk * 33 + tx * 4 + 1];
            float w2_ = s_w[kk * 33 + tx * 4 + 2];
            float w3_ = s_w[kk * 33 + tx * 4 + 3];
            acc[0][0] += a0 * w0; acc[0][1] += a0 * w1_;
            acc[0][2] += a0 * w2_; acc[0][3] += a0 * w3_;
            acc[1][0] += a1 * w0; acc[1][1] += a1 * w1_;
            acc[1][2] += a1 * w2_; acc[1][3] += a1 * w3_;
        }
    }

#pragma unroll
    for (int j = 0; j < 4; j++) {
        int col = bn + tx * 4 + j;
        float bias = b4[col];
#pragma unroll
        for (int i = 0; i < 2; i++) {
            int row = bm + ty * 2 + i;
            g_feat[row * 256 + col] = fmaxf(acc[i][j] + bias, 0.f);
        }
    }
}

// ============================================================================
// head: latent = feat @ enc_w^T + enc_b ; log_alpha = latent @ sink_w^T + b ;
// stopping = softmax(latent @ mask_w^T + b).  grid 64, block 256 (16 imgs).
// ============================================================================
__global__ __launch_bounds__(256) void head_kernel(
    const float* __restrict__ enc_w, const float* __restrict__ enc_b,
    const float* __restrict__ sink_w, const float* __restrict__ sink_b,
    const float* __restrict__ mask_w, const float* __restrict__ mask_b,
    float* __restrict__ out_stop)
{
    __shared__ float s_encw[16 * 257];
    __shared__ float s_feat[16][256];
    __shared__ float s_sw[576], s_sb[36], s_mw[96], s_mb[6];
    __shared__ float s_lat[16][16];

    const int t  = threadIdx.x;
    const int b0 = blockIdx.x * 16;

    for (int e = t; e < 4096; e += 256) {
        int l = e >> 8, i = e & 255;
        s_encw[l * 257 + i] = enc_w[e];
        s_feat[l][i] = g_feat[(b0 + l) * 256 + i];
    }
    for (int e = t; e < 576; e += 256) s_sw[e] = sink_w[e];
    if (t < 36) s_sb[t] = sink_b[t];
    for (int e = t; e < 96; e += 256) s_mw[e] = mask_w[e];
    if (t < 6) s_mb[t] = mask_b[t];
    __syncthreads();

    const int bl = t >> 4;
    const int l  = t & 15;
    const int b  = b0 + bl;

    float lat = enc_b[l];
#pragma unroll 8
    for (int i = 0; i < 256; i++)
        lat += s_feat[bl][i] * s_encw[l * 257 + i];
    s_lat[bl][l] = lat;
    __syncthreads();

    for (int rr = l; rr < 36; rr += 16) {
        float la = s_sb[rr];
#pragma unroll
        for (int i = 0; i < 16; i++) la += s_lat[bl][i] * s_sw[rr * 16 + i];
        g_logalpha[b * 36 + rr] = la;
    }

    if (l == 0) {
        float lg[6];
        float mx = -1e30f;
#pragma unroll
        for (int k = 0; k < 6; k++) {
            float v = s_mb[k];
#pragma unroll
            for (int i = 0; i < 16; i++) v += s_lat[bl][i] * s_mw[k * 16 + i];
            lg[k] = v;
            mx = fmaxf(mx, v);
        }
        float sum = 0.f;
#pragma unroll
        for (int k = 0; k < 6; k++) { lg[k] = expf(lg[k] - mx); sum += lg[k]; }
        float inv = 1.f / sum;
#pragma unroll
        for (int k = 0; k < 6; k++) out_stop[b * 6 + k] = lg[k] * inv;
    }
}

// ============================================================================
// sinkhorn: one thread per 6x6 matrix (8192 total), 20 iterations in regs,
// then ordered[m,k] = sum_j exp(la[j,k]) * seq[b,j].
// ============================================================================
__global__ __launch_bounds__(256) void sinkhorn_kernel(
    const float* __restrict__ gn, const float* __restrict__ seq,
    float* __restrict__ out_ordered)
{
    const int m = blockIdx.x * 256 + threadIdx.x;   // 0..8191
    const int b = m & (BATCH - 1);

    float la[36];
#pragma unroll
    for (int i = 0; i < 36; i++)
        la[i] = g_logalpha[b * 36 + i] + gn[m * 36 + i];

    float sq[6];
#pragma unroll
    for (int j = 0; j < 6; j++) sq[j] = seq[b * 6 + j];

#pragma unroll 1
    for (int it = 0; it < NITERS; it++) {
        // row normalize (over k)
#pragma unroll
        for (int j = 0; j < 6; j++) {
            float mx = la[j * 6];
#pragma unroll
            for (int k = 1; k < 6; k++) mx = fmaxf(mx, la[j * 6 + k]);
            float s = 0.f;
#pragma unroll
            for (int k = 0; k < 6; k++) s += expf(la[j * 6 + k] - mx);
            float lse = mx + logf(s);
#pragma unroll
            for (int k = 0; k < 6; k++) la[j * 6 + k] -= lse;
        }
        // col normalize (over j)
#pragma unroll
        for (int k = 0; k < 6; k++) {
            float mx = la[k];
#pragma unroll
            for (int j = 1; j < 6; j++) mx = fmaxf(mx, la[j * 6 + k]);
            float s = 0.f;
#pragma unroll
            for (int j = 0; j < 6; j++) s += expf(la[j * 6 + k] - mx);
            float lse = mx + logf(s);
#pragma unroll
            for (int j = 0; j < 6; j++) la[j * 6 + k] -= lse;
        }
    }

#pragma unroll
    for (int k = 0; k < 6; k++) {
        float o = 0.f;
#pragma unroll
        for (int j = 0; j < 6; j++) o += expf(la[j * 6 + k]) * sq[j];
        out_ordered[m * 6 + k] = o;
    }
}

// ============================================================================
extern "C" void kernel_launch(void* const* d_in, const int* in_sizes, int n_in,
                              void* d_out, int out_size)
{
    const float* seq    = (const float*)d_in[0];
    const float* im     = (const float*)d_in[1];
    const float* gn     = (const float*)d_in[2];
    const float* w1     = (const float*)d_in[3];
    const float* b1     = (const float*)d_in[4];
    const float* w2     = (const float*)d_in[5];
    const float* b2     = (const float*)d_in[6];
    const float* w3     = (const float*)d_in[7];
    const float* b3     = (const float*)d_in[8];
    const float* w4     = (const float*)d_in[9];
    const float* b4     = (const float*)d_in[10];
    const float* enc_w  = (const float*)d_in[11];
    const float* enc_b  = (const float*)d_in[12];
    const float* sink_w = (const float*)d_in[13];
    const float* sink_b = (const float*)d_in[14];
    const float* mask_w = (const float*)d_in[15];
    const float* mask_b = (const float*)d_in[16];

    float* out = (float*)d_out;
    float* out_ordered = out;                         // [8192*6]
    float* out_stop    = out + NSAMP * BATCH * KDIM;  // [1024*6]

    conv1_kernel<<<dim3(BATCH, 4), 256>>>(im, w1, b1);
    conv2_kernel<<<BATCH, 352>>>(w2, b2);
    conv3_kernel<<<BATCH, 128>>>(w3, b3);
    conv4_kernel<<<dim3(16, 8), 256>>>(w4, b4);
    head_kernel<<<64, 256>>>(enc_w, enc_b, sink_w, sink_b, mask_w, mask_b, out_stop);
    sinkhorn_kernel<<<32, 256>>>(gn, seq, out_ordered);
}

// round 5
// speedup vs baseline: 1.5155x; 1.5155x over previous
#include <cuda_runtime.h>
#include <cuda_bf16.h>
#include <cstdint>

// ---------------- problem constants ----------------
#define BATCH   1024
#define NSAMP   8
#define KDIM    6
#define NITERS  20

// ---------------- scratch (device globals; no allocs allowed) ----------------
__device__ float g_act1[BATCH * 32 * 30 * 30];   // conv1 out fp32
__device__ float g_act2[BATCH * 64 * 13 * 13];   // conv2 out fp32
__device__ float g_act3[BATCH * 128 * 5 * 5];    // conv3 out fp32
__device__ float g_featp[4 * BATCH * 256];       // conv4 split-K partials
__device__ float g_logalpha[BATCH * 36];

// ============================================================================
// helpers
// ============================================================================
__device__ __forceinline__ void bf16_split(float v, __nv_bfloat16& h, __nv_bfloat16& l) {
    h = __float2bfloat16(v);
    l = __float2bfloat16(v - __bfloat162float(h));
}
__device__ __forceinline__ uint32_t pack2(__nv_bfloat16 a, __nv_bfloat16 b) {
    return (uint32_t)__bfloat16_as_ushort(a) | ((uint32_t)__bfloat16_as_ushort(b) << 16);
}
// m16n8k16 row.col bf16 -> f32, accumulate in place
__device__ __forceinline__ void mma16816(float* d, const uint32_t* a, const uint32_t* b) {
    asm volatile(
        "mma.sync.aligned.m16n8k16.row.col.f32.bf16.bf16.f32 "
        "{%0,%1,%2,%3}, {%4,%5,%6,%7}, {%8,%9}, {%0,%1,%2,%3};"
        : "+f"(d[0]), "+f"(d[1]), "+f"(d[2]), "+f"(d[3])
        : "r"(a[0]), "r"(a[1]), "r"(a[2]), "r"(a[3]), "r"(b[0]), "r"(b[1]));
}

// ============================================================================
// conv1 (scalar fp32): [B,3,64,64] -> [B,32,30,30]   (verified R2)
// ============================================================================
__global__ __launch_bounds__(256) void conv1_kernel(
    const float* __restrict__ im, const float* __restrict__ w1,
    const float* __restrict__ b1)
{
    __shared__ float s_in[64 * 64];
    __shared__ float s_w[8 * 75];

    const int b   = blockIdx.x;
    const int oc0 = blockIdx.y * 8;
    const int t   = threadIdx.x;

    for (int i = t; i < 600; i += 256) s_w[i] = w1[oc0 * 75 + i];

    float acc[4][8];
#pragma unroll
    for (int i = 0; i < 4; i++)
#pragma unroll
        for (int o = 0; o < 8; o++) acc[i][o] = 0.f;

    int bo[4]; bool val[4];
#pragma unroll
    for (int i = 0; i < 4; i++) {
        int p = t + 256 * i;
        val[i] = (p < 900);
        int oy = p / 30, ox = p % 30;
        bo[i] = val[i] ? (2 * oy * 64 + 2 * ox) : 0;
    }

#pragma unroll 1
    for (int c = 0; c < 3; c++) {
        __syncthreads();
        const float4* src = reinterpret_cast<const float4*>(im + (b * 3 + c) * 4096);
        float4* dst = reinterpret_cast<float4*>(s_in);
        for (int e = t; e < 1024; e += 256) dst[e] = src[e];
        __syncthreads();

#pragma unroll
        for (int ky = 0; ky < 5; ky++) {
#pragma unroll
            for (int kx = 0; kx < 5; kx++) {
                float w8[8];
#pragma unroll
                for (int o = 0; o < 8; o++)
                    w8[o] = s_w[o * 75 + c * 25 + ky * 5 + kx];
#pragma unroll
                for (int i = 0; i < 4; i++) {
                    float v = s_in[bo[i] + ky * 64 + kx];
#pragma unroll
                    for (int o = 0; o < 8; o++) acc[i][o] += v * w8[o];
                }
            }
        }
    }

#pragma unroll
    for (int o = 0; o < 8; o++) {
        float bias = b1[oc0 + o];
#pragma unroll
        for (int i = 0; i < 4; i++) {
            int p = t + 256 * i;
            if (val[i])
                g_act1[(b * 32 + oc0 + o) * 900 + p] = fmaxf(acc[i][o] + bias, 0.f);
        }
    }
}

// ============================================================================
// conv2 via mma.sync: per-image GEMM
//   D[pos 169->192, oc 64] = im2col[pos, 32ch*32pad] @ w2^T, bf16 hi/lo 3-pass
// grid 1024, block 256 (8 warps = 4m x 2n; warp tile 48x32).
// smem (bf16 elems): Ah[192*40] Al[192*40] Bh[64*40] Bl[64*40] ph[900] pl[900]
// ============================================================================
#define C2_SMEM_BF16 (7680*2 + 2560*2 + 900*2)   // 22280 elems = 44560 B

__global__ __launch_bounds__(256) void conv2_mma(
    const float* __restrict__ w2, const float* __restrict__ b2)
{
    extern __shared__ __nv_bfloat16 s2[];
    __nv_bfloat16* Ah = s2;
    __nv_bfloat16* Al = s2 + 7680;
    __nv_bfloat16* Bh = s2 + 15360;
    __nv_bfloat16* Bl = s2 + 17920;
    __nv_bfloat16* ph = s2 + 20480;
    __nv_bfloat16* pl = s2 + 21380;

    const int b = blockIdx.x, t = threadIdx.x;
    const int wid = t >> 5, lane = t & 31, g = lane >> 2, tq = lane & 3;
    const int wm = wid >> 1, wn = wid & 1;   // 4 x 2 warp grid

    // zero A/B tile region (20480 bf16 = 10240 u32): pad rows/cols stay 0 forever
    for (int i = t; i < 10240; i += 256) reinterpret_cast<uint32_t*>(s2)[i] = 0u;

    float acc[3][4][4];
#pragma unroll
    for (int mt = 0; mt < 3; mt++)
#pragma unroll
        for (int nt = 0; nt < 4; nt++)
#pragma unroll
            for (int i = 0; i < 4; i++) acc[mt][nt][i] = 0.f;

#pragma unroll 1
    for (int c = 0; c < 32; c++) {
        __syncthreads();   // prev chunk's LDS reads done before overwriting

        // stage one input plane fp32 -> bf16 hi/lo
        const float* p0 = g_act1 + (b * 32 + c) * 900;
        for (int i = t; i < 900; i += 256) {
            __nv_bfloat16 h, l;
            bf16_split(p0[i], h, l);
            ph[i] = h; pl[i] = l;
        }
        __syncthreads();

        // im2col A rows (169 units, 1/thread)
        if (t < 169) {
            const int oy = t / 13, ox = t % 13;
            const int ib = oy * 60 + ox * 2;
            const int rb = t * 40;
#pragma unroll
            for (int j2 = 0; j2 < 13; j2++) {
                const int k0 = 2 * j2;
                const int o0 = (k0 / 5) * 30 + (k0 % 5);
                __nv_bfloat16 h0 = ph[ib + o0], l0 = pl[ib + o0];
                __nv_bfloat16 h1, l1;
                if (k0 + 1 < 25) {
                    const int o1 = ((k0 + 1) / 5) * 30 + ((k0 + 1) % 5);
                    h1 = ph[ib + o1]; l1 = pl[ib + o1];
                } else {
                    h1 = __ushort_as_bfloat16(0); l1 = __ushort_as_bfloat16(0);
                }
                *reinterpret_cast<uint32_t*>(&Ah[rb + k0]) = pack2(h0, h1);
                *reinterpret_cast<uint32_t*>(&Al[rb + k0]) = pack2(l0, l1);
            }
        }
        // B rows (64 oc)
        if (t < 64) {
            const float* ws = w2 + t * 800 + c * 25;
            const int rb = t * 40;
#pragma unroll
            for (int j2 = 0; j2 < 13; j2++) {
                const int k0 = 2 * j2;
                float v0 = ws[k0];
                float v1 = (k0 + 1 < 25) ? ws[k0 + 1] : 0.f;
                __nv_bfloat16 h0, l0, h1, l1;
                bf16_split(v0, h0, l0);
                bf16_split(v1, h1, l1);
                *reinterpret_cast<uint32_t*>(&Bh[rb + k0]) = pack2(h0, h1);
                *reinterpret_cast<uint32_t*>(&Bl[rb + k0]) = pack2(l0, l1);
            }
        }
        __syncthreads();

#pragma unroll
        for (int ks = 0; ks < 2; ks++) {
            const int kc = ks * 16;
            uint32_t a[3][4], bh[4][2], bl[4][2];
#pragma unroll
            for (int mt = 0; mt < 3; mt++) {
                const int r = wm * 48 + mt * 16;
                a[mt][0] = *reinterpret_cast<uint32_t*>(&Ah[(r + g) * 40 + kc + 2 * tq]);
                a[mt][1] = *reinterpret_cast<uint32_t*>(&Ah[(r + g + 8) * 40 + kc + 2 * tq]);
                a[mt][2] = *reinterpret_cast<uint32_t*>(&Ah[(r + g) * 40 + kc + 2 * tq + 8]);
                a[mt][3] = *reinterpret_cast<uint32_t*>(&Ah[(r + g + 8) * 40 + kc + 2 * tq + 8]);
            }
#pragma unroll
            for (int nt = 0; nt < 4; nt++) {
                const int n = wn * 32 + nt * 8 + g;
                bh[nt][0] = *reinterpret_cast<uint32_t*>(&Bh[n * 40 + kc + 2 * tq]);
                bh[nt][1] = *reinterpret_cast<uint32_t*>(&Bh[n * 40 + kc + 2 * tq + 8]);
                bl[nt][0] = *reinterpret_cast<uint32_t*>(&Bl[n * 40 + kc + 2 * tq]);
                bl[nt][1] = *reinterpret_cast<uint32_t*>(&Bl[n * 40 + kc + 2 * tq + 8]);
            }
#pragma unroll
            for (int mt = 0; mt < 3; mt++)
#pragma unroll
                for (int nt = 0; nt < 4; nt++) {
                    mma16816(acc[mt][nt], a[mt], bh[nt]);
                    mma16816(acc[mt][nt], a[mt], bl[nt]);
                }
            // A_lo pass
#pragma unroll
            for (int mt = 0; mt < 3; mt++) {
                const int r = wm * 48 + mt * 16;
                a[mt][0] = *reinterpret_cast<uint32_t*>(&Al[(r + g) * 40 + kc + 2 * tq]);
                a[mt][1] = *reinterpret_cast<uint32_t*>(&Al[(r + g + 8) * 40 + kc + 2 * tq]);
                a[mt][2] = *reinterpret_cast<uint32_t*>(&Al[(r + g) * 40 + kc + 2 * tq + 8]);
                a[mt][3] = *reinterpret_cast<uint32_t*>(&Al[(r + g + 8) * 40 + kc + 2 * tq + 8]);
            }
#pragma unroll
            for (int mt = 0; mt < 3; mt++)
#pragma unroll
                for (int nt = 0; nt < 4; nt++)
                    mma16816(acc[mt][nt], a[mt], bh[nt]);
        }
    }

    // epilogue: bias + relu, write g_act2[b][oc][pos]
    float* dst = g_act2 + b * 64 * 169;
#pragma unroll
    for (int mt = 0; mt < 3; mt++) {
        const int r0 = wm * 48 + mt * 16 + g;
        const int r1 = r0 + 8;
#pragma unroll
        for (int nt = 0; nt < 4; nt++) {
            const int n0 = wn * 32 + nt * 8 + 2 * tq;
            const float bi0 = b2[n0], bi1 = b2[n0 + 1];
            if (r0 < 169) {
                dst[n0 * 169 + r0]       = fmaxf(acc[mt][nt][0] + bi0, 0.f);
                dst[(n0 + 1) * 169 + r0] = fmaxf(acc[mt][nt][1] + bi1, 0.f);
            }
            if (r1 < 169) {
                dst[n0 * 169 + r1]       = fmaxf(acc[mt][nt][2] + bi0, 0.f);
                dst[(n0 + 1) * 169 + r1] = fmaxf(acc[mt][nt][3] + bi1, 0.f);
            }
        }
    }
}

// ============================================================================
// conv3 via mma.sync: 5 images/CTA
//   D[r = img*25+pos (125->128), oc 128] = im2col[r, 64ch*32pad] @ w3^T
// grid 205, block 256 (8 warps = 2m x 4n; warp tile 64x32).
// smem (bf16): Ah[128*40] Al[128*40] Bh[128*40] Bl[128*40] ph[845] pl[845]
// ============================================================================
#define C3_SMEM_BF16 (5120*4 + 845*2)   // 22170 elems = 44340 B

__global__ __launch_bounds__(256) void conv3_mma(
    const float* __restrict__ w3, const float* __restrict__ b3)
{
    extern __shared__ __nv_bfloat16 s3[];
    __nv_bfloat16* Ah = s3;
    __nv_bfloat16* Al = s3 + 5120;
    __nv_bfloat16* Bh = s3 + 10240;
    __nv_bfloat16* Bl = s3 + 15360;
    __nv_bfloat16* ph = s3 + 20480;
    __nv_bfloat16* pl = s3 + 21325;

    const int t = threadIdx.x;
    const int wid = t >> 5, lane = t & 31, g = lane >> 2, tq = lane & 3;
    const int wm = wid >> 2, wn = wid & 3;   // 2 x 4 warp grid
    const int b0 = blockIdx.x * 5;
    const int nimg = (BATCH - b0 < 5) ? (BATCH - b0) : 5;

    for (int i = t; i < 10240; i += 256) reinterpret_cast<uint32_t*>(s3)[i] = 0u;

    float acc[4][4][4];
#pragma unroll
    for (int mt = 0; mt < 4; mt++)
#pragma unroll
        for (int nt = 0; nt < 4; nt++)
#pragma unroll
            for (int i = 0; i < 4; i++) acc[mt][nt][i] = 0.f;

#pragma unroll 1
    for (int c = 0; c < 64; c++) {
        __syncthreads();

        // stage 5 planes of channel c
        for (int i = t; i < 845; i += 256) {
            const int il = i / 169, idx = i % 169;
            if (il < nimg) {
                __nv_bfloat16 h, l;
                bf16_split(g_act2[((b0 + il) * 64 + c) * 169 + idx], h, l);
                ph[i] = h; pl[i] = l;
            }
        }
        __syncthreads();

        // im2col A (125 rows)
        if (t < 125) {
            const int il = t / 25, p = t % 25;
            if (il < nimg) {
                const int oy = p / 5, ox = p % 5;
                const int ib = il * 169 + oy * 26 + ox * 2;
                const int rb = t * 40;
#pragma unroll
                for (int j2 = 0; j2 < 13; j2++) {
                    const int k0 = 2 * j2;
                    const int o0 = (k0 / 5) * 13 + (k0 % 5);
                    __nv_bfloat16 h0 = ph[ib + o0], l0 = pl[ib + o0];
                    __nv_bfloat16 h1, l1;
                    if (k0 + 1 < 25) {
                        const int o1 = ((k0 + 1) / 5) * 13 + ((k0 + 1) % 5);
                        h1 = ph[ib + o1]; l1 = pl[ib + o1];
                    } else {
                        h1 = __ushort_as_bfloat16(0); l1 = __ushort_as_bfloat16(0);
                    }
                    *reinterpret_cast<uint32_t*>(&Ah[rb + k0]) = pack2(h0, h1);
                    *reinterpret_cast<uint32_t*>(&Al[rb + k0]) = pack2(l0, l1);
                }
            }
        }
        // B (128 oc)
        if (t < 128) {
            const float* ws = w3 + t * 1600 + c * 25;
            const int rb = t * 40;
#pragma unroll
            for (int j2 = 0; j2 < 13; j2++) {
                const int k0 = 2 * j2;
                float v0 = ws[k0];
                float v1 = (k0 + 1 < 25) ? ws[k0 + 1] : 0.f;
                __nv_bfloat16 h0, l0, h1, l1;
                bf16_split(v0, h0, l0);
                bf16_split(v1, h1, l1);
                *reinterpret_cast<uint32_t*>(&Bh[rb + k0]) = pack2(h0, h1);
                *reinterpret_cast<uint32_t*>(&Bl[rb + k0]) = pack2(l0, l1);
            }
        }
        __syncthreads();

#pragma unroll
        for (int ks = 0; ks < 2; ks++) {
            const int kc = ks * 16;
            uint32_t a[4][4], bh[4][2], bl[4][2];
#pragma unroll
            for (int mt = 0; mt < 4; mt++) {
                const int r = wm * 64 + mt * 16;
                a[mt][0] = *reinterpret_cast<uint32_t*>(&Ah[(r + g) * 40 + kc + 2 * tq]);
                a[mt][1] = *reinterpret_cast<uint32_t*>(&Ah[(r + g + 8) * 40 + kc + 2 * tq]);
                a[mt][2] = *reinterpret_cast<uint32_t*>(&Ah[(r + g) * 40 + kc + 2 * tq + 8]);
                a[mt][3] = *reinterpret_cast<uint32_t*>(&Ah[(r + g + 8) * 40 + kc + 2 * tq + 8]);
            }
#pragma unroll
            for (int nt = 0; nt < 4; nt++) {
                const int n = wn * 32 + nt * 8 + g;
                bh[nt][0] = *reinterpret_cast<uint32_t*>(&Bh[n * 40 + kc + 2 * tq]);
                bh[nt][1] = *reinterpret_cast<uint32_t*>(&Bh[n * 40 + kc + 2 * tq + 8]);
                bl[nt][0] = *reinterpret_cast<uint32_t*>(&Bl[n * 40 + kc + 2 * tq]);
                bl[nt][1] = *reinterpret_cast<uint32_t*>(&Bl[n * 40 + kc + 2 * tq + 8]);
            }
#pragma unroll
            for (int mt = 0; mt < 4; mt++)
#pragma unroll
                for (int nt = 0; nt < 4; nt++) {
                    mma16816(acc[mt][nt], a[mt], bh[nt]);
                    mma16816(acc[mt][nt], a[mt], bl[nt]);
                }
#pragma unroll
            for (int mt = 0; mt < 4; mt++) {
                const int r = wm * 64 + mt * 16;
                a[mt][0] = *reinterpret_cast<uint32_t*>(&Al[(r + g) * 40 + kc + 2 * tq]);
                a[mt][1] = *reinterpret_cast<uint32_t*>(&Al[(r + g + 8) * 40 + kc + 2 * tq]);
                a[mt][2] = *reinterpret_cast<uint32_t*>(&Al[(r + g) * 40 + kc + 2 * tq + 8]);
                a[mt][3] = *reinterpret_cast<uint32_t*>(&Al[(r + g + 8) * 40 + kc + 2 * tq + 8]);
            }
#pragma unroll
            for (int mt = 0; mt < 4; mt++)
#pragma unroll
                for (int nt = 0; nt < 4; nt++)
                    mma16816(acc[mt][nt], a[mt], bh[nt]);
        }
    }

    // epilogue
#pragma unroll
    for (int mt = 0; mt < 4; mt++) {
#pragma unroll
        for (int nt = 0; nt < 4; nt++) {
            const int n0 = wn * 32 + nt * 8 + 2 * tq;
            const float bi0 = b3[n0], bi1 = b3[n0 + 1];
#pragma unroll
            for (int half = 0; half < 2; half++) {
                const int r = wm * 64 + mt * 16 + g + half * 8;
                if (r < 125) {
                    const int il = r / 25, p = r % 25;
                    if (il < nimg) {
                        float* o = g_act3 + ((b0 + il) * 128) * 25 + p;
                        o[n0 * 25]       = fmaxf(acc[mt][nt][half * 2 + 0] + bi0, 0.f);
                        o[(n0 + 1) * 25] = fmaxf(acc[mt][nt][half * 2 + 1] + bi1, 0.f);
                    }
                }
            }
        }
    }
}

// ============================================================================
// conv4: split-K scalar GEMM partials. C[1024,256] = A[1024,3200] @ W^T.
// grid (16,4,4): BM=64, BN=64, K-chunk=800. Thread tile 4x4.
// ============================================================================
__global__ __launch_bounds__(256) void conv4_kernel(
    const float* __restrict__ w4)
{
    __shared__ float s_a[32 * 68];
    __shared__ float s_w[32 * 68];

    const int bm = blockIdx.x * 64;
    const int bn = blockIdx.y * 64;
    const int kz = blockIdx.z;
    const int t  = threadIdx.x;
    const int tx = t & 15;
    const int ty = t >> 4;

    const float* A = g_act3;

    float acc[4][4];
#pragma unroll
    for (int i = 0; i < 4; i++)
#pragma unroll
        for (int j = 0; j < 4; j++) acc[i][j] = 0.f;

#pragma unroll 1
    for (int k0 = kz * 800; k0 < kz * 800 + 800; k0 += 32) {
        __syncthreads();
        for (int e = t; e < 2048; e += 256) {
            int r = e >> 5, kk = e & 31;
            s_a[kk * 68 + r] = A[(bm + r) * 3200 + k0 + kk];
            s_w[kk * 68 + r] = w4[(bn + r) * 3200 + k0 + kk];
        }
        __syncthreads();

#pragma unroll 4
        for (int kk = 0; kk < 32; kk++) {
            float4 av = *reinterpret_cast<const float4*>(&s_a[kk * 68 + ty * 4]);
            float4 wv = *reinterpret_cast<const float4*>(&s_w[kk * 68 + tx * 4]);
            float a[4] = {av.x, av.y, av.z, av.w};
            float w[4] = {wv.x, wv.y, wv.z, wv.w};
#pragma unroll
            for (int i = 0; i < 4; i++)
#pragma unroll
                for (int j = 0; j < 4; j++) acc[i][j] += a[i] * w[j];
        }
    }

    float* dst = g_featp + kz * (BATCH * 256);
#pragma unroll
    for (int i = 0; i < 4; i++)
#pragma unroll
        for (int j = 0; j < 4; j++)
            dst[(bm + ty * 4 + i) * 256 + (bn + tx * 4 + j)] = acc[i][j];
}

// ============================================================================
// head: feat = relu(sum_z partials + b4); latent; log_alpha; stopping softmax
// ============================================================================
__global__ __launch_bounds__(256) void head_kernel(
    const float* __restrict__ b4,
    const float* __restrict__ enc_w, const float* __restrict__ enc_b,
    const float* __restrict__ sink_w, const float* __restrict__ sink_b,
    const float* __restrict__ mask_w, const float* __restrict__ mask_b,
    float* __restrict__ out_stop)
{
    __shared__ float s_encw[16 * 257];
    __shared__ float s_feat[16][256];
    __shared__ float s_sw[576], s_sb[36], s_mw[96], s_mb[6];
    __shared__ float s_lat[16][16];

    const int t  = threadIdx.x;
    const int b0 = blockIdx.x * 16;

    for (int e = t; e < 4096; e += 256) {
        int l = e >> 8, i = e & 255;
        s_encw[l * 257 + i] = enc_w[e];
        float v = b4[i];
#pragma unroll
        for (int z = 0; z < 4; z++)
            v += g_featp[z * (BATCH * 256) + (b0 + l) * 256 + i];
        s_feat[l][i] = fmaxf(v, 0.f);
    }
    for (int e = t; e < 576; e += 256) s_sw[e] = sink_w[e];
    if (t < 36) s_sb[t] = sink_b[t];
    for (int e = t; e < 96; e += 256) s_mw[e] = mask_w[e];
    if (t < 6) s_mb[t] = mask_b[t];
    __syncthreads();

    const int bl = t >> 4;
    const int l  = t & 15;
    const int b  = b0 + bl;

    float lat = enc_b[l];
#pragma unroll 8
    for (int i = 0; i < 256; i++)
        lat += s_feat[bl][i] * s_encw[l * 257 + i];
    s_lat[bl][l] = lat;
    __syncthreads();

    for (int rr = l; rr < 36; rr += 16) {
        float la = s_sb[rr];
#pragma unroll
        for (int i = 0; i < 16; i++) la += s_lat[bl][i] * s_sw[rr * 16 + i];
        g_logalpha[b * 36 + rr] = la;
    }

    if (l == 0) {
        float lg[6];
        float mx = -1e30f;
#pragma unroll
        for (int k = 0; k < 6; k++) {
            float v = s_mb[k];
#pragma unroll
            for (int i = 0; i < 16; i++) v += s_lat[bl][i] * s_mw[k * 16 + i];
            lg[k] = v;
            mx = fmaxf(mx, v);
        }
        float sum = 0.f;
#pragma unroll
        for (int k = 0; k < 6; k++) { lg[k] = expf(lg[k] - mx); sum += lg[k]; }
        float inv = 1.f / sum;
#pragma unroll
        for (int k = 0; k < 6; k++) out_stop[b * 6 + k] = lg[k] * inv;
    }
}

// ============================================================================
// sinkhorn: one thread per 6x6 matrix (8192 total)
// ============================================================================
__global__ __launch_bounds__(256) void sinkhorn_kernel(
    const float* __restrict__ gn, const float* __restrict__ seq,
    float* __restrict__ out_ordered)
{
    const int m = blockIdx.x * 256 + threadIdx.x;
    const int b = m & (BATCH - 1);

    float la[36];
#pragma unroll
    for (int i = 0; i < 36; i++)
        la[i] = g_logalpha[b * 36 + i] + gn[m * 36 + i];

    float sq[6];
#pragma unroll
    for (int j = 0; j < 6; j++) sq[j] = seq[b * 6 + j];

#pragma unroll 1
    for (int it = 0; it < NITERS; it++) {
#pragma unroll
        for (int j = 0; j < 6; j++) {
            float mx = la[j * 6];
#pragma unroll
            for (int k = 1; k < 6; k++) mx = fmaxf(mx, la[j * 6 + k]);
            float s = 0.f;
#pragma unroll
            for (int k = 0; k < 6; k++) s += expf(la[j * 6 + k] - mx);
            float lse = mx + logf(s);
#pragma unroll
            for (int k = 0; k < 6; k++) la[j * 6 + k] -= lse;
        }
#pragma unroll
        for (int k = 0; k < 6; k++) {
            float mx = la[k];
#pragma unroll
            for (int j = 1; j < 6; j++) mx = fmaxf(mx, la[j * 6 + k]);
            float s = 0.f;
#pragma unroll
            for (int j = 0; j < 6; j++) s += expf(la[j * 6 + k] - mx);
            float lse = mx + logf(s);
#pragma unroll
            for (int j = 0; j < 6; j++) la[j * 6 + k] -= lse;
        }
    }

#pragma unroll
    for (int k = 0; k < 6; k++) {
        float o = 0.f;
#pragma unroll
        for (int j = 0; j < 6; j++) o += expf(la[j * 6 + k]) * sq[j];
        out_ordered[m * 6 + k] = o;
    }
}

// ============================================================================
extern "C" void kernel_launch(void* const* d_in, const int* in_sizes, int n_in,
                              void* d_out, int out_size)
{
    const float* seq    = (const float*)d_in[0];
    const float* im     = (const float*)d_in[1];
    const float* gn     = (const float*)d_in[2];
    const float* w1     = (const float*)d_in[3];
    const float* b1     = (const float*)d_in[4];
    const float* w2     = (const float*)d_in[5];
    const float* b2     = (const float*)d_in[6];
    const float* w3     = (const float*)d_in[7];
    const float* b3     = (const float*)d_in[8];
    const float* w4     = (const float*)d_in[9];
    const float* b4     = (const float*)d_in[10];
    const float* enc_w  = (const float*)d_in[11];
    const float* enc_b  = (const float*)d_in[12];
    const float* sink_w = (const float*)d_in[13];
    const float* sink_b = (const float*)d_in[14];
    const float* mask_w = (const float*)d_in[15];
    const float* mask_b = (const float*)d_in[16];

    float* out = (float*)d_out;
    float* out_ordered = out;                         // [8192*6]
    float* out_stop    = out + NSAMP * BATCH * KDIM;  // [1024*6]

    conv1_kernel<<<dim3(BATCH, 4), 256>>>(im, w1, b1);
    conv2_mma<<<BATCH, 256, C2_SMEM_BF16 * 2>>>(w2, b2);
    conv3_mma<<<205, 256, C3_SMEM_BF16 * 2>>>(w3, b3);
    conv4_kernel<<<dim3(16, 4, 4), 256>>>(w4);
    head_kernel<<<64, 256>>>(b4, enc_w, enc_b, sink_w, sink_b, mask_w, mask_b, out_stop);
    sinkhorn_kernel<<<32, 256>>>(gn, seq, out_ordered);
}

// round 6
// speedup vs baseline: 1.9859x; 1.3104x over previous
#include <cuda_runtime.h>
#include <cuda_bf16.h>
#include <cstdint>

// ---------------- problem constants ----------------
#define BATCH   1024
#define NSAMP   8
#define KDIM    6
#define NITERS  20
#define KZ4     10          // conv4 split-K factor

// ---------------- scratch (device globals; no allocs allowed) ----------------
__device__ float g_act1[BATCH * 32 * 30 * 30];
__device__ float g_act2[BATCH * 64 * 13 * 13];
__device__ float g_act3[BATCH * 128 * 5 * 5];
__device__ float g_featp[KZ4 * BATCH * 256];
__device__ float g_logalpha[BATCH * 36];

// ============================================================================
// helpers
// ============================================================================
__device__ __forceinline__ void bf16_split(float v, __nv_bfloat16& h, __nv_bfloat16& l) {
    h = __float2bfloat16(v);
    l = __float2bfloat16(v - __bfloat162float(h));
}
__device__ __forceinline__ uint32_t pack2(__nv_bfloat16 a, __nv_bfloat16 b) {
    return (uint32_t)__bfloat16_as_ushort(a) | ((uint32_t)__bfloat16_as_ushort(b) << 16);
}
__device__ __forceinline__ void mma16816(float* d, const uint32_t* a, const uint32_t* b) {
    asm volatile(
        "mma.sync.aligned.m16n8k16.row.col.f32.bf16.bf16.f32 "
        "{%0,%1,%2,%3}, {%4,%5,%6,%7}, {%8,%9}, {%0,%1,%2,%3};"
        : "+f"(d[0]), "+f"(d[1]), "+f"(d[2]), "+f"(d[3])
        : "r"(a[0]), "r"(a[1]), "r"(a[2]), "r"(a[3]), "r"(b[0]), "r"(b[1]));
}

// ============================================================================
// conv1 (scalar fp32): [B,3,64,64] -> [B,32,30,30].  16 oc per CTA.
// grid (1024, 2), block 256.  Thread: 4 pos x 16 oc.
// ============================================================================
__global__ __launch_bounds__(256) void conv1_kernel(
    const float* __restrict__ im, const float* __restrict__ w1,
    const float* __restrict__ b1)
{
    __shared__ float s_in[64 * 64];
    __shared__ float s_w[16 * 75];

    const int b   = blockIdx.x;
    const int oc0 = blockIdx.y * 16;
    const int t   = threadIdx.x;

    for (int i = t; i < 1200; i += 256) s_w[i] = w1[oc0 * 75 + i];

    float acc[4][16];
#pragma unroll
    for (int i = 0; i < 4; i++)
#pragma unroll
        for (int o = 0; o < 16; o++) acc[i][o] = 0.f;

    int bo[4]; bool val[4];
#pragma unroll
    for (int i = 0; i < 4; i++) {
        int p = t + 256 * i;
        val[i] = (p < 900);
        int oy = p / 30, ox = p % 30;
        bo[i] = val[i] ? (2 * oy * 64 + 2 * ox) : 0;
    }

#pragma unroll 1
    for (int c = 0; c < 3; c++) {
        __syncthreads();
        const float4* src = reinterpret_cast<const float4*>(im + (b * 3 + c) * 4096);
        float4* dst = reinterpret_cast<float4*>(s_in);
        for (int e = t; e < 1024; e += 256) dst[e] = src[e];
        __syncthreads();

#pragma unroll 1
        for (int ky = 0; ky < 5; ky++) {
#pragma unroll
            for (int kx = 0; kx < 5; kx++) {
                float w16[16];
#pragma unroll
                for (int o = 0; o < 16; o++)
                    w16[o] = s_w[o * 75 + c * 25 + ky * 5 + kx];
#pragma unroll
                for (int i = 0; i < 4; i++) {
                    float v = s_in[bo[i] + ky * 64 + kx];
#pragma unroll
                    for (int o = 0; o < 16; o++) acc[i][o] += v * w16[o];
                }
            }
        }
    }

#pragma unroll
    for (int o = 0; o < 16; o++) {
        float bias = b1[oc0 + o];
#pragma unroll
        for (int i = 0; i < 4; i++) {
            int p = t + 256 * i;
            if (val[i])
                g_act1[(b * 32 + oc0 + o) * 900 + p] = fmaxf(acc[i][o] + bias, 0.f);
        }
    }
}

// ============================================================================
// conv2 via mma.sync, software-pipelined staging.
//   D[pos 169->192, oc 64] = im2col @ w2^T, bf16 hi/lo 3-pass.
// grid 1024, block 256 (8 warps = 4m x 2n; warp tile 48x32).
// ============================================================================
#define C2_SMEM_BF16 (7680*2 + 2560*2 + 900*2)   // 44560 B

__global__ __launch_bounds__(256) void conv2_mma(
    const float* __restrict__ w2, const float* __restrict__ b2)
{
    extern __shared__ __nv_bfloat16 s2[];
    __nv_bfloat16* Ah = s2;
    __nv_bfloat16* Al = s2 + 7680;
    __nv_bfloat16* Bh = s2 + 15360;
    __nv_bfloat16* Bl = s2 + 17920;
    __nv_bfloat16* ph = s2 + 20480;
    __nv_bfloat16* pl = s2 + 21380;

    const int b = blockIdx.x, t = threadIdx.x;
    const int wid = t >> 5, lane = t & 31, g = lane >> 2, tq = lane & 3;
    const int wm = wid >> 1, wn = wid & 1;

    for (int i = t; i < 10240; i += 256) reinterpret_cast<uint32_t*>(s2)[i] = 0u;

    float acc[3][4][4];
#pragma unroll
    for (int mt = 0; mt < 3; mt++)
#pragma unroll
        for (int nt = 0; nt < 4; nt++)
#pragma unroll
            for (int i = 0; i < 4; i++) acc[mt][nt][i] = 0.f;

    const float* src = g_act1 + b * 32 * 900;   // 900 floats per channel, 16B-aligned
    float4 pf = make_float4(0.f, 0.f, 0.f, 0.f);
    if (t < 225) pf = reinterpret_cast<const float4*>(src)[t];   // prefetch c=0

#pragma unroll 1
    for (int c = 0; c < 32; c++) {
        // store prefetched plane (split hi/lo)
        if (t < 225) {
            __nv_bfloat16 h, l;
            bf16_split(pf.x, h, l); ph[4*t+0] = h; pl[4*t+0] = l;
            bf16_split(pf.y, h, l); ph[4*t+1] = h; pl[4*t+1] = l;
            bf16_split(pf.z, h, l); ph[4*t+2] = h; pl[4*t+2] = l;
            bf16_split(pf.w, h, l); ph[4*t+3] = h; pl[4*t+3] = l;
        }
        __syncthreads();

        // prefetch next channel (latency overlaps build+MMA)
        if (c + 1 < 32 && t < 225)
            pf = reinterpret_cast<const float4*>(src + (c + 1) * 900)[t];

        // build A (t<169) and B (169<=t<233), disjoint threads
        if (t < 169) {
            const int oy = t / 13, ox = t % 13;
            const int ib = oy * 60 + ox * 2;
            const int rb = t * 40;
#pragma unroll
            for (int j2 = 0; j2 < 13; j2++) {
                const int k0 = 2 * j2;
                const int o0 = (k0 / 5) * 30 + (k0 % 5);
                __nv_bfloat16 h0 = ph[ib + o0], l0 = pl[ib + o0];
                __nv_bfloat16 h1, l1;
                if (k0 + 1 < 25) {
                    const int o1 = ((k0 + 1) / 5) * 30 + ((k0 + 1) % 5);
                    h1 = ph[ib + o1]; l1 = pl[ib + o1];
                } else {
                    h1 = __ushort_as_bfloat16(0); l1 = __ushort_as_bfloat16(0);
                }
                *reinterpret_cast<uint32_t*>(&Ah[rb + k0]) = pack2(h0, h1);
                *reinterpret_cast<uint32_t*>(&Al[rb + k0]) = pack2(l0, l1);
            }
        } else if (t < 233) {
            const int oc = t - 169;
            const float* ws = w2 + oc * 800 + c * 25;
            const int rb = oc * 40;
#pragma unroll
            for (int j2 = 0; j2 < 13; j2++) {
                const int k0 = 2 * j2;
                float v0 = ws[k0];
                float v1 = (k0 + 1 < 25) ? ws[k0 + 1] : 0.f;
                __nv_bfloat16 h0, l0, h1, l1;
                bf16_split(v0, h0, l0);
                bf16_split(v1, h1, l1);
                *reinterpret_cast<uint32_t*>(&Bh[rb + k0]) = pack2(h0, h1);
                *reinterpret_cast<uint32_t*>(&Bl[rb + k0]) = pack2(l0, l1);
            }
        }
        __syncthreads();

#pragma unroll
        for (int ks = 0; ks < 2; ks++) {
            const int kc = ks * 16;
            uint32_t a[3][4], bh[4][2], bl[4][2];
#pragma unroll
            for (int mt = 0; mt < 3; mt++) {
                const int r = wm * 48 + mt * 16;
                a[mt][0] = *reinterpret_cast<uint32_t*>(&Ah[(r + g) * 40 + kc + 2 * tq]);
                a[mt][1] = *reinterpret_cast<uint32_t*>(&Ah[(r + g + 8) * 40 + kc + 2 * tq]);
                a[mt][2] = *reinterpret_cast<uint32_t*>(&Ah[(r + g) * 40 + kc + 2 * tq + 8]);
                a[mt][3] = *reinterpret_cast<uint32_t*>(&Ah[(r + g + 8) * 40 + kc + 2 * tq + 8]);
            }
#pragma unroll
            for (int nt = 0; nt < 4; nt++) {
                const int n = wn * 32 + nt * 8 + g;
                bh[nt][0] = *reinterpret_cast<uint32_t*>(&Bh[n * 40 + kc + 2 * tq]);
                bh[nt][1] = *reinterpret_cast<uint32_t*>(&Bh[n * 40 + kc + 2 * tq + 8]);
                bl[nt][0] = *reinterpret_cast<uint32_t*>(&Bl[n * 40 + kc + 2 * tq]);
                bl[nt][1] = *reinterpret_cast<uint32_t*>(&Bl[n * 40 + kc + 2 * tq + 8]);
            }
#pragma unroll
            for (int mt = 0; mt < 3; mt++)
#pragma unroll
                for (int nt = 0; nt < 4; nt++) {
                    mma16816(acc[mt][nt], a[mt], bh[nt]);
                    mma16816(acc[mt][nt], a[mt], bl[nt]);
                }
#pragma unroll
            for (int mt = 0; mt < 3; mt++) {
                const int r = wm * 48 + mt * 16;
                a[mt][0] = *reinterpret_cast<uint32_t*>(&Al[(r + g) * 40 + kc + 2 * tq]);
                a[mt][1] = *reinterpret_cast<uint32_t*>(&Al[(r + g + 8) * 40 + kc + 2 * tq]);
                a[mt][2] = *reinterpret_cast<uint32_t*>(&Al[(r + g) * 40 + kc + 2 * tq + 8]);
                a[mt][3] = *reinterpret_cast<uint32_t*>(&Al[(r + g + 8) * 40 + kc + 2 * tq + 8]);
            }
#pragma unroll
            for (int mt = 0; mt < 3; mt++)
#pragma unroll
                for (int nt = 0; nt < 4; nt++)
                    mma16816(acc[mt][nt], a[mt], bh[nt]);
        }
        __syncthreads();   // A/B free to overwrite next iter
    }

    float* dst = g_act2 + b * 64 * 169;
#pragma unroll
    for (int mt = 0; mt < 3; mt++) {
        const int r0 = wm * 48 + mt * 16 + g;
        const int r1 = r0 + 8;
#pragma unroll
        for (int nt = 0; nt < 4; nt++) {
            const int n0 = wn * 32 + nt * 8 + 2 * tq;
            const float bi0 = b2[n0], bi1 = b2[n0 + 1];
            if (r0 < 169) {
                dst[n0 * 169 + r0]       = fmaxf(acc[mt][nt][0] + bi0, 0.f);
                dst[(n0 + 1) * 169 + r0] = fmaxf(acc[mt][nt][1] + bi1, 0.f);
            }
            if (r1 < 169) {
                dst[n0 * 169 + r1]       = fmaxf(acc[mt][nt][2] + bi0, 0.f);
                dst[(n0 + 1) * 169 + r1] = fmaxf(acc[mt][nt][3] + bi1, 0.f);
            }
        }
    }
}

// ============================================================================
// conv3 via mma.sync, software-pipelined staging. 5 images/CTA.
// grid 205, block 256 (8 warps = 2m x 4n; warp tile 64x32).
// ============================================================================
#define C3_SMEM_BF16 (5120*4 + 845*2)   // 44340 B

__global__ __launch_bounds__(256) void conv3_mma(
    const float* __restrict__ w3, const float* __restrict__ b3)
{
    extern __shared__ __nv_bfloat16 s3[];
    __nv_bfloat16* Ah = s3;
    __nv_bfloat16* Al = s3 + 5120;
    __nv_bfloat16* Bh = s3 + 10240;
    __nv_bfloat16* Bl = s3 + 15360;
    __nv_bfloat16* ph = s3 + 20480;
    __nv_bfloat16* pl = s3 + 21325;

    const int t = threadIdx.x;
    const int wid = t >> 5, lane = t & 31, g = lane >> 2, tq = lane & 3;
    const int wm = wid >> 2, wn = wid & 3;
    const int b0 = blockIdx.x * 5;
    const int nimg = (BATCH - b0 < 5) ? (BATCH - b0) : 5;

    for (int i = t; i < 10240; i += 256) reinterpret_cast<uint32_t*>(s3)[i] = 0u;

    float acc[4][4][4];
#pragma unroll
    for (int mt = 0; mt < 4; mt++)
#pragma unroll
        for (int nt = 0; nt < 4; nt++)
#pragma unroll
            for (int i = 0; i < 4; i++) acc[mt][nt][i] = 0.f;

    // prefetch channel 0: 845 floats, 4 scalars per thread
    float pf[4];
    int pfil[4], pfidx[4]; bool pfv[4];
#pragma unroll
    for (int k = 0; k < 4; k++) {
        const int i = t + 256 * k;
        pfv[k]   = (i < 845);
        pfil[k]  = pfv[k] ? (i / 169) : 0;
        pfidx[k] = pfv[k] ? (i % 169) : 0;
        pfv[k]   = pfv[k] && (pfil[k] < nimg);
        pf[k] = pfv[k] ? g_act2[((b0 + pfil[k]) * 64 + 0) * 169 + pfidx[k]] : 0.f;
    }

#pragma unroll 1
    for (int c = 0; c < 64; c++) {
#pragma unroll
        for (int k = 0; k < 4; k++) {
            const int i = t + 256 * k;
            if (i < 845) {
                __nv_bfloat16 h, l;
                bf16_split(pf[k], h, l);
                ph[i] = h; pl[i] = l;
            }
        }
        __syncthreads();

        if (c + 1 < 64) {
#pragma unroll
            for (int k = 0; k < 4; k++)
                if (pfv[k])
                    pf[k] = g_act2[((b0 + pfil[k]) * 64 + (c + 1)) * 169 + pfidx[k]];
        }

        // build A (t<125) and B (125<=t<253), disjoint
        if (t < 125) {
            const int il = t / 25, p = t % 25;
            if (il < nimg) {
                const int oy = p / 5, ox = p % 5;
                const int ib = il * 169 + oy * 26 + ox * 2;
                const int rb = t * 40;
#pragma unroll
                for (int j2 = 0; j2 < 13; j2++) {
                    const int k0 = 2 * j2;
                    const int o0 = (k0 / 5) * 13 + (k0 % 5);
                    __nv_bfloat16 h0 = ph[ib + o0], l0 = pl[ib + o0];
                    __nv_bfloat16 h1, l1;
                    if (k0 + 1 < 25) {
                        const int o1 = ((k0 + 1) / 5) * 13 + ((k0 + 1) % 5);
                        h1 = ph[ib + o1]; l1 = pl[ib + o1];
                    } else {
                        h1 = __ushort_as_bfloat16(0); l1 = __ushort_as_bfloat16(0);
                    }
                    *reinterpret_cast<uint32_t*>(&Ah[rb + k0]) = pack2(h0, h1);
                    *reinterpret_cast<uint32_t*>(&Al[rb + k0]) = pack2(l0, l1);
                }
            }
        } else if (t < 253) {
            const int oc = t - 125;
            const float* ws = w3 + oc * 1600 + c * 25;
            const int rb = oc * 40;
#pragma unroll
            for (int j2 = 0; j2 < 13; j2++) {
                const int k0 = 2 * j2;
                float v0 = ws[k0];
                float v1 = (k0 + 1 < 25) ? ws[k0 + 1] : 0.f;
                __nv_bfloat16 h0, l0, h1, l1;
                bf16_split(v0, h0, l0);
                bf16_split(v1, h1, l1);
                *reinterpret_cast<uint32_t*>(&Bh[rb + k0]) = pack2(h0, h1);
                *reinterpret_cast<uint32_t*>(&Bl[rb + k0]) = pack2(l0, l1);
            }
        }
        __syncthreads();

#pragma unroll
        for (int ks = 0; ks < 2; ks++) {
            const int kc = ks * 16;
            uint32_t a[4][4], bh[4][2], bl[4][2];
#pragma unroll
            for (int mt = 0; mt < 4; mt++) {
                const int r = wm * 64 + mt * 16;
                a[mt][0] = *reinterpret_cast<uint32_t*>(&Ah[(r + g) * 40 + kc + 2 * tq]);
                a[mt][1] = *reinterpret_cast<uint32_t*>(&Ah[(r + g + 8) * 40 + kc + 2 * tq]);
                a[mt][2] = *reinterpret_cast<uint32_t*>(&Ah[(r + g) * 40 + kc + 2 * tq + 8]);
                a[mt][3] = *reinterpret_cast<uint32_t*>(&Ah[(r + g + 8) * 40 + kc + 2 * tq + 8]);
            }
#pragma unroll
            for (int nt = 0; nt < 4; nt++) {
                const int n = wn * 32 + nt * 8 + g;
                bh[nt][0] = *reinterpret_cast<uint32_t*>(&Bh[n * 40 + kc + 2 * tq]);
                bh[nt][1] = *reinterpret_cast<uint32_t*>(&Bh[n * 40 + kc + 2 * tq + 8]);
                bl[nt][0] = *reinterpret_cast<uint32_t*>(&Bl[n * 40 + kc + 2 * tq]);
                bl[nt][1] = *reinterpret_cast<uint32_t*>(&Bl[n * 40 + kc + 2 * tq + 8]);
            }
#pragma unroll
            for (int mt = 0; mt < 4; mt++)
#pragma unroll
                for (int nt = 0; nt < 4; nt++) {
                    mma16816(acc[mt][nt], a[mt], bh[nt]);
                    mma16816(acc[mt][nt], a[mt], bl[nt]);
                }
#pragma unroll
            for (int mt = 0; mt < 4; mt++) {
                const int r = wm * 64 + mt * 16;
                a[mt][0] = *reinterpret_cast<uint32_t*>(&Al[(r + g) * 40 + kc + 2 * tq]);
                a[mt][1] = *reinterpret_cast<uint32_t*>(&Al[(r + g + 8) * 40 + kc + 2 * tq]);
                a[mt][2] = *reinterpret_cast<uint32_t*>(&Al[(r + g) * 40 + kc + 2 * tq + 8]);
                a[mt][3] = *reinterpret_cast<uint32_t*>(&Al[(r + g + 8) * 40 + kc + 2 * tq + 8]);
            }
#pragma unroll
            for (int mt = 0; mt < 4; mt++)
#pragma unroll
                for (int nt = 0; nt < 4; nt++)
                    mma16816(acc[mt][nt], a[mt], bh[nt]);
        }
        __syncthreads();
    }

#pragma unroll
    for (int mt = 0; mt < 4; mt++) {
#pragma unroll
        for (int nt = 0; nt < 4; nt++) {
            const int n0 = wn * 32 + nt * 8 + 2 * tq;
            const float bi0 = b3[n0], bi1 = b3[n0 + 1];
#pragma unroll
            for (int half = 0; half < 2; half++) {
                const int r = wm * 64 + mt * 16 + g + half * 8;
                if (r < 125) {
                    const int il = r / 25, p = r % 25;
                    if (il < nimg) {
                        float* o = g_act3 + ((b0 + il) * 128) * 25 + p;
                        o[n0 * 25]       = fmaxf(acc[mt][nt][half * 2 + 0] + bi0, 0.f);
                        o[(n0 + 1) * 25] = fmaxf(acc[mt][nt][half * 2 + 1] + bi1, 0.f);
                    }
                }
            }
        }
    }
}

// ============================================================================
// conv4: split-K x10 scalar GEMM partials. grid (16,4,10), chunk 320.
// ============================================================================
__global__ __launch_bounds__(256) void conv4_kernel(
    const float* __restrict__ w4)
{
    __shared__ float s_a[32 * 68];
    __shared__ float s_w[32 * 68];

    const int bm = blockIdx.x * 64;
    const int bn = blockIdx.y * 64;
    const int kz = blockIdx.z;
    const int t  = threadIdx.x;
    const int tx = t & 15;
    const int ty = t >> 4;

    const float* A = g_act3;

    float acc[4][4];
#pragma unroll
    for (int i = 0; i < 4; i++)
#pragma unroll
        for (int j = 0; j < 4; j++) acc[i][j] = 0.f;

#pragma unroll 1
    for (int k0 = kz * 320; k0 < kz * 320 + 320; k0 += 32) {
        __syncthreads();
        for (int e = t; e < 2048; e += 256) {
            int r = e >> 5, kk = e & 31;
            s_a[kk * 68 + r] = A[(bm + r) * 3200 + k0 + kk];
            s_w[kk * 68 + r] = w4[(bn + r) * 3200 + k0 + kk];
        }
        __syncthreads();

#pragma unroll 4
        for (int kk = 0; kk < 32; kk++) {
            float4 av = *reinterpret_cast<const float4*>(&s_a[kk * 68 + ty * 4]);
            float4 wv = *reinterpret_cast<const float4*>(&s_w[kk * 68 + tx * 4]);
            float a[4] = {av.x, av.y, av.z, av.w};
            float w[4] = {wv.x, wv.y, wv.z, wv.w};
#pragma unroll
            for (int i = 0; i < 4; i++)
#pragma unroll
                for (int j = 0; j < 4; j++) acc[i][j] += a[i] * w[j];
        }
    }

    float* dst = g_featp + kz * (BATCH * 256);
#pragma unroll
    for (int i = 0; i < 4; i++)
#pragma unroll
        for (int j = 0; j < 4; j++)
            dst[(bm + ty * 4 + i) * 256 + (bn + tx * 4 + j)] = acc[i][j];
}

// ============================================================================
// head: feat = relu(sum_z partials + b4); latent; log_alpha; stopping softmax
// ============================================================================
__global__ __launch_bounds__(256) void head_kernel(
    const float* __restrict__ b4,
    const float* __restrict__ enc_w, const float* __restrict__ enc_b,
    const float* __restrict__ sink_w, const float* __restrict__ sink_b,
    const float* __restrict__ mask_w, const float* __restrict__ mask_b,
    float* __restrict__ out_stop)
{
    __shared__ float s_encw[16 * 257];
    __shared__ float s_feat[16][256];
    __shared__ float s_sw[576], s_sb[36], s_mw[96], s_mb[6];
    __shared__ float s_lat[16][16];

    const int t  = threadIdx.x;
    const int b0 = blockIdx.x * 16;

    for (int e = t; e < 4096; e += 256) {
        int l = e >> 8, i = e & 255;
        s_encw[l * 257 + i] = enc_w[e];
        float v = b4[i];
#pragma unroll
        for (int z = 0; z < KZ4; z++)
            v += g_featp[z * (BATCH * 256) + (b0 + l) * 256 + i];
        s_feat[l][i] = fmaxf(v, 0.f);
    }
    for (int e = t; e < 576; e += 256) s_sw[e] = sink_w[e];
    if (t < 36) s_sb[t] = sink_b[t];
    for (int e = t; e < 96; e += 256) s_mw[e] = mask_w[e];
    if (t < 6) s_mb[t] = mask_b[t];
    __syncthreads();

    const int bl = t >> 4;
    const int l  = t & 15;
    const int b  = b0 + bl;

    float lat = enc_b[l];
#pragma unroll 8
    for (int i = 0; i < 256; i++)
        lat += s_feat[bl][i] * s_encw[l * 257 + i];
    s_lat[bl][l] = lat;
    __syncthreads();

    for (int rr = l; rr < 36; rr += 16) {
        float la = s_sb[rr];
#pragma unroll
        for (int i = 0; i < 16; i++) la += s_lat[bl][i] * s_sw[rr * 16 + i];
        g_logalpha[b * 36 + rr] = la;
    }

    if (l == 0) {
        float lg[6];
        float mx = -1e30f;
#pragma unroll
        for (int k = 0; k < 6; k++) {
            float v = s_mb[k];
#pragma unroll
            for (int i = 0; i < 16; i++) v += s_lat[bl][i] * s_mw[k * 16 + i];
            lg[k] = v;
            mx = fmaxf(mx, v);
        }
        float sum = 0.f;
#pragma unroll
        for (int k = 0; k < 6; k++) { lg[k] = __expf(lg[k] - mx); sum += lg[k]; }
        float inv = 1.f / sum;
#pragma unroll
        for (int k = 0; k < 6; k++) out_stop[b * 6 + k] = lg[k] * inv;
    }
}

// ============================================================================
// sinkhorn: one thread per 6x6 matrix (8192 total), fast exp/log
// ============================================================================
__global__ __launch_bounds__(256) void sinkhorn_kernel(
    const float* __restrict__ gn, const float* __restrict__ seq,
    float* __restrict__ out_ordered)
{
    const int m = blockIdx.x * 256 + threadIdx.x;
    const int b = m & (BATCH - 1);

    float la[36];
#pragma unroll
    for (int i = 0; i < 36; i++)
        la[i] = g_logalpha[b * 36 + i] + gn[m * 36 + i];

    float sq[6];
#pragma unroll
    for (int j = 0; j < 6; j++) sq[j] = seq[b * 6 + j];

#pragma unroll 1
    for (int it = 0; it < NITERS; it++) {
#pragma unroll
        for (int j = 0; j < 6; j++) {
            float mx = la[j * 6];
#pragma unroll
            for (int k = 1; k < 6; k++) mx = fmaxf(mx, la[j * 6 + k]);
            float s = 0.f;
#pragma unroll
            for (int k = 0; k < 6; k++) s += __expf(la[j * 6 + k] - mx);
            float lse = mx + __logf(s);
#pragma unroll
            for (int k = 0; k < 6; k++) la[j * 6 + k] -= lse;
        }
#pragma unroll
        for (int k = 0; k < 6; k++) {
            float mx = la[k];
#pragma unroll
            for (int j = 1; j < 6; j++) mx = fmaxf(mx, la[j * 6 + k]);
            float s = 0.f;
#pragma unroll
            for (int j = 0; j < 6; j++) s += __expf(la[j * 6 + k] - mx);
            float lse = mx + __logf(s);
#pragma unroll
            for (int j = 0; j < 6; j++) la[j * 6 + k] -= lse;
        }
    }

#pragma unroll
    for (int k = 0; k < 6; k++) {
        float o = 0.f;
#pragma unroll
        for (int j = 0; j < 6; j++) o += __expf(la[j * 6 + k]) * sq[j];
        out_ordered[m * 6 + k] = o;
    }
}

// ============================================================================
extern "C" void kernel_launch(void* const* d_in, const int* in_sizes, int n_in,
                              void* d_out, int out_size)
{
    const float* seq    = (const float*)d_in[0];
    const float* im     = (const float*)d_in[1];
    const float* gn     = (const float*)d_in[2];
    const float* w1     = (const float*)d_in[3];
    const float* b1     = (const float*)d_in[4];
    const float* w2     = (const float*)d_in[5];
    const float* b2     = (const float*)d_in[6];
    const float* w3     = (const float*)d_in[7];
    const float* b3     = (const float*)d_in[8];
    const float* w4     = (const float*)d_in[9];
    const float* b4     = (const float*)d_in[10];
    const float* enc_w  = (const float*)d_in[11];
    const float* enc_b  = (const float*)d_in[12];
    const float* sink_w = (const float*)d_in[13];
    const float* sink_b = (const float*)d_in[14];
    const float* mask_w = (const float*)d_in[15];
    const float* mask_b = (const float*)d_in[16];

    float* out = (float*)d_out;
    float* out_ordered = out;                         // [8192*6]
    float* out_stop    = out + NSAMP * BATCH * KDIM;  // [1024*6]

    conv1_kernel<<<dim3(BATCH, 2), 256>>>(im, w1, b1);
    conv2_mma<<<BATCH, 256, C2_SMEM_BF16 * 2>>>(w2, b2);
    conv3_mma<<<205, 256, C3_SMEM_BF16 * 2>>>(w3, b3);
    conv4_kernel<<<dim3(16, 4, KZ4), 256>>>(w4);
    head_kernel<<<64, 256>>>(b4, enc_w, enc_b, sink_w, sink_b, mask_w, mask_b, out_stop);
    sinkhorn_kernel<<<32, 256>>>(gn, seq, out_ordered);
}

// round 7
// speedup vs baseline: 2.0525x; 1.0335x over previous
#include <cuda_runtime.h>
#include <cuda_bf16.h>
#include <cstdint>

// ---------------- problem constants ----------------
#define BATCH   1024
#define NSAMP   8
#define KDIM    6
#define NITERS  20
#define KZ4     10          // conv4 split-K factor

// ---------------- scratch (device globals; no allocs allowed) ----------------
__device__ float g_act1[BATCH * 32 * 30 * 30];
__device__ float g_act2[BATCH * 64 * 13 * 13];
__device__ float g_act3[BATCH * 128 * 5 * 5];
__device__ float g_featp[KZ4 * BATCH * 256];
__device__ float g_logalpha[BATCH * 36];

// ============================================================================
// helpers
// ============================================================================
__device__ __forceinline__ void bf16_split(float v, __nv_bfloat16& h, __nv_bfloat16& l) {
    h = __float2bfloat16(v);
    l = __float2bfloat16(v - __bfloat162float(h));
}
__device__ __forceinline__ uint32_t pack2(__nv_bfloat16 a, __nv_bfloat16 b) {
    return (uint32_t)__bfloat16_as_ushort(a) | ((uint32_t)__bfloat16_as_ushort(b) << 16);
}
__device__ __forceinline__ void mma16816(float* d, const uint32_t* a, const uint32_t* b) {
    asm volatile(
        "mma.sync.aligned.m16n8k16.row.col.f32.bf16.bf16.f32 "
        "{%0,%1,%2,%3}, {%4,%5,%6,%7}, {%8,%9}, {%0,%1,%2,%3};"
        : "+f"(d[0]), "+f"(d[1]), "+f"(d[2]), "+f"(d[3])
        : "r"(a[0]), "r"(a[1]), "r"(a[2]), "r"(a[3]), "r"(b[0]), "r"(b[1]));
}

// ============================================================================
// conv1 (scalar fp32): [B,3,64,64] -> [B,32,30,30].  16 oc per CTA.
// grid (1024, 2), block 256.  Thread: 4 pos x 16 oc.
// ============================================================================
__global__ __launch_bounds__(256, 2) void conv1_kernel(
    const float* __restrict__ im, const float* __restrict__ w1,
    const float* __restrict__ b1)
{
    __shared__ float s_in[64 * 64];
    __shared__ float s_w[16 * 75];

    const int b   = blockIdx.x;
    const int oc0 = blockIdx.y * 16;
    const int t   = threadIdx.x;

    for (int i = t; i < 1200; i += 256) s_w[i] = w1[oc0 * 75 + i];

    float acc[4][16];
#pragma unroll
    for (int i = 0; i < 4; i++)
#pragma unroll
        for (int o = 0; o < 16; o++) acc[i][o] = 0.f;

    int bo[4]; bool val[4];
#pragma unroll
    for (int i = 0; i < 4; i++) {
        int p = t + 256 * i;
        val[i] = (p < 900);
        int oy = p / 30, ox = p % 30;
        bo[i] = val[i] ? (2 * oy * 64 + 2 * ox) : 0;
    }

#pragma unroll 1
    for (int c = 0; c < 3; c++) {
        __syncthreads();
        const float4* src = reinterpret_cast<const float4*>(im + (b * 3 + c) * 4096);
        float4* dst = reinterpret_cast<float4*>(s_in);
        for (int e = t; e < 1024; e += 256) dst[e] = src[e];
        __syncthreads();

#pragma unroll 1
        for (int ky = 0; ky < 5; ky++) {
#pragma unroll
            for (int kx = 0; kx < 5; kx++) {
                float w16[16];
#pragma unroll
                for (int o = 0; o < 16; o++)
                    w16[o] = s_w[o * 75 + c * 25 + ky * 5 + kx];
#pragma unroll
                for (int i = 0; i < 4; i++) {
                    float v = s_in[bo[i] + ky * 64 + kx];
#pragma unroll
                    for (int o = 0; o < 16; o++) acc[i][o] += v * w16[o];
                }
            }
        }
    }

#pragma unroll
    for (int o = 0; o < 16; o++) {
        float bias = b1[oc0 + o];
#pragma unroll
        for (int i = 0; i < 4; i++) {
            int p = t + 256 * i;
            if (val[i])
                g_act1[(b * 32 + oc0 + o) * 900 + p] = fmaxf(acc[i][o] + bias, 0.f);
        }
    }
}

// ============================================================================
// conv2 via mma.sync, software-pipelined staging.
//   D[pos 169->192, oc 64] = im2col @ w2^T, bf16 hi/lo 3-pass.
// grid 1024, block 256 (8 warps = 4m x 2n; warp tile 48x32).
// __launch_bounds__(256,2): cap regs at 128 so 2 CTAs/SM co-reside and
// one CTA's build/sync overlaps the other's MMA phase.
// ============================================================================
#define C2_SMEM_BF16 (7680*2 + 2560*2 + 900*2)   // 44560 B

__global__ __launch_bounds__(256, 2) void conv2_mma(
    const float* __restrict__ w2, const float* __restrict__ b2)
{
    extern __shared__ __nv_bfloat16 s2[];
    __nv_bfloat16* Ah = s2;
    __nv_bfloat16* Al = s2 + 7680;
    __nv_bfloat16* Bh = s2 + 15360;
    __nv_bfloat16* Bl = s2 + 17920;
    __nv_bfloat16* ph = s2 + 20480;
    __nv_bfloat16* pl = s2 + 21380;

    const int b = blockIdx.x, t = threadIdx.x;
    const int wid = t >> 5, lane = t & 31, g = lane >> 2, tq = lane & 3;
    const int wm = wid >> 1, wn = wid & 1;

    for (int i = t; i < 10240; i += 256) reinterpret_cast<uint32_t*>(s2)[i] = 0u;

    float acc[3][4][4];
#pragma unroll
    for (int mt = 0; mt < 3; mt++)
#pragma unroll
        for (int nt = 0; nt < 4; nt++)
#pragma unroll
            for (int i = 0; i < 4; i++) acc[mt][nt][i] = 0.f;

    const float* src = g_act1 + b * 32 * 900;
    float4 pf = make_float4(0.f, 0.f, 0.f, 0.f);
    if (t < 225) pf = reinterpret_cast<const float4*>(src)[t];

#pragma unroll 1
    for (int c = 0; c < 32; c++) {
        if (t < 225) {
            __nv_bfloat16 h, l;
            bf16_split(pf.x, h, l); ph[4*t+0] = h; pl[4*t+0] = l;
            bf16_split(pf.y, h, l); ph[4*t+1] = h; pl[4*t+1] = l;
            bf16_split(pf.z, h, l); ph[4*t+2] = h; pl[4*t+2] = l;
            bf16_split(pf.w, h, l); ph[4*t+3] = h; pl[4*t+3] = l;
        }
        __syncthreads();

        if (c + 1 < 32 && t < 225)
            pf = reinterpret_cast<const float4*>(src + (c + 1) * 900)[t];

        if (t < 169) {
            const int oy = t / 13, ox = t % 13;
            const int ib = oy * 60 + ox * 2;
            const int rb = t * 40;
#pragma unroll
            for (int j2 = 0; j2 < 13; j2++) {
                const int k0 = 2 * j2;
                const int o0 = (k0 / 5) * 30 + (k0 % 5);
                __nv_bfloat16 h0 = ph[ib + o0], l0 = pl[ib + o0];
                __nv_bfloat16 h1, l1;
                if (k0 + 1 < 25) {
                    const int o1 = ((k0 + 1) / 5) * 30 + ((k0 + 1) % 5);
                    h1 = ph[ib + o1]; l1 = pl[ib + o1];
                } else {
                    h1 = __ushort_as_bfloat16(0); l1 = __ushort_as_bfloat16(0);
                }
                *reinterpret_cast<uint32_t*>(&Ah[rb + k0]) = pack2(h0, h1);
                *reinterpret_cast<uint32_t*>(&Al[rb + k0]) = pack2(l0, l1);
            }
        } else if (t < 233) {
            const int oc = t - 169;
            const float* ws = w2 + oc * 800 + c * 25;
            const int rb = oc * 40;
#pragma unroll
            for (int j2 = 0; j2 < 13; j2++) {
                const int k0 = 2 * j2;
                float v0 = ws[k0];
                float v1 = (k0 + 1 < 25) ? ws[k0 + 1] : 0.f;
                __nv_bfloat16 h0, l0, h1, l1;
                bf16_split(v0, h0, l0);
                bf16_split(v1, h1, l1);
                *reinterpret_cast<uint32_t*>(&Bh[rb + k0]) = pack2(h0, h1);
                *reinterpret_cast<uint32_t*>(&Bl[rb + k0]) = pack2(l0, l1);
            }
        }
        __syncthreads();

#pragma unroll
        for (int ks = 0; ks < 2; ks++) {
            const int kc = ks * 16;
            uint32_t a[3][4], bh[4][2], bl[4][2];
#pragma unroll
            for (int mt = 0; mt < 3; mt++) {
                const int r = wm * 48 + mt * 16;
                a[mt][0] = *reinterpret_cast<uint32_t*>(&Ah[(r + g) * 40 + kc + 2 * tq]);
                a[mt][1] = *reinterpret_cast<uint32_t*>(&Ah[(r + g + 8) * 40 + kc + 2 * tq]);
                a[mt][2] = *reinterpret_cast<uint32_t*>(&Ah[(r + g) * 40 + kc + 2 * tq + 8]);
                a[mt][3] = *reinterpret_cast<uint32_t*>(&Ah[(r + g + 8) * 40 + kc + 2 * tq + 8]);
            }
#pragma unroll
            for (int nt = 0; nt < 4; nt++) {
                const int n = wn * 32 + nt * 8 + g;
                bh[nt][0] = *reinterpret_cast<uint32_t*>(&Bh[n * 40 + kc + 2 * tq]);
                bh[nt][1] = *reinterpret_cast<uint32_t*>(&Bh[n * 40 + kc + 2 * tq + 8]);
                bl[nt][0] = *reinterpret_cast<uint32_t*>(&Bl[n * 40 + kc + 2 * tq]);
                bl[nt][1] = *reinterpret_cast<uint32_t*>(&Bl[n * 40 + kc + 2 * tq + 8]);
            }
#pragma unroll
            for (int mt = 0; mt < 3; mt++)
#pragma unroll
                for (int nt = 0; nt < 4; nt++) {
                    mma16816(acc[mt][nt], a[mt], bh[nt]);
                    mma16816(acc[mt][nt], a[mt], bl[nt]);
                }
#pragma unroll
            for (int mt = 0; mt < 3; mt++) {
                const int r = wm * 48 + mt * 16;
                a[mt][0] = *reinterpret_cast<uint32_t*>(&Al[(r + g) * 40 + kc + 2 * tq]);
                a[mt][1] = *reinterpret_cast<uint32_t*>(&Al[(r + g + 8) * 40 + kc + 2 * tq]);
                a[mt][2] = *reinterpret_cast<uint32_t*>(&Al[(r + g) * 40 + kc + 2 * tq + 8]);
                a[mt][3] = *reinterpret_cast<uint32_t*>(&Al[(r + g + 8) * 40 + kc + 2 * tq + 8]);
            }
#pragma unroll
            for (int mt = 0; mt < 3; mt++)
#pragma unroll
                for (int nt = 0; nt < 4; nt++)
                    mma16816(acc[mt][nt], a[mt], bh[nt]);
        }
        __syncthreads();
    }

    float* dst = g_act2 + b * 64 * 169;
#pragma unroll
    for (int mt = 0; mt < 3; mt++) {
        const int r0 = wm * 48 + mt * 16 + g;
        const int r1 = r0 + 8;
#pragma unroll
        for (int nt = 0; nt < 4; nt++) {
            const int n0 = wn * 32 + nt * 8 + 2 * tq;
            const float bi0 = b2[n0], bi1 = b2[n0 + 1];
            if (r0 < 169) {
                dst[n0 * 169 + r0]       = fmaxf(acc[mt][nt][0] + bi0, 0.f);
                dst[(n0 + 1) * 169 + r0] = fmaxf(acc[mt][nt][1] + bi1, 0.f);
            }
            if (r1 < 169) {
                dst[n0 * 169 + r1]       = fmaxf(acc[mt][nt][2] + bi0, 0.f);
                dst[(n0 + 1) * 169 + r1] = fmaxf(acc[mt][nt][3] + bi1, 0.f);
            }
        }
    }
}

// ============================================================================
// conv3 via mma.sync, software-pipelined staging. 5 images/CTA.
// grid 205, block 256 (8 warps = 2m x 4n; warp tile 64x32).
// __launch_bounds__(256,2) for 2 CTAs/SM.
// ============================================================================
#define C3_SMEM_BF16 (5120*4 + 845*2)   // 44340 B

__global__ __launch_bounds__(256, 2) void conv3_mma(
    const float* __restrict__ w3, const float* __restrict__ b3)
{
    extern __shared__ __nv_bfloat16 s3[];
    __nv_bfloat16* Ah = s3;
    __nv_bfloat16* Al = s3 + 5120;
    __nv_bfloat16* Bh = s3 + 10240;
    __nv_bfloat16* Bl = s3 + 15360;
    __nv_bfloat16* ph = s3 + 20480;
    __nv_bfloat16* pl = s3 + 21325;

    const int t = threadIdx.x;
    const int wid = t >> 5, lane = t & 31, g = lane >> 2, tq = lane & 3;
    const int wm = wid >> 2, wn = wid & 3;
    const int b0 = blockIdx.x * 5;
    const int nimg = (BATCH - b0 < 5) ? (BATCH - b0) : 5;

    for (int i = t; i < 10240; i += 256) reinterpret_cast<uint32_t*>(s3)[i] = 0u;

    float acc[4][4][4];
#pragma unroll
    for (int mt = 0; mt < 4; mt++)
#pragma unroll
        for (int nt = 0; nt < 4; nt++)
#pragma unroll
            for (int i = 0; i < 4; i++) acc[mt][nt][i] = 0.f;

    float pf[4];
    int pfil[4], pfidx[4]; bool pfv[4];
#pragma unroll
    for (int k = 0; k < 4; k++) {
        const int i = t + 256 * k;
        pfv[k]   = (i < 845);
        pfil[k]  = pfv[k] ? (i / 169) : 0;
        pfidx[k] = pfv[k] ? (i % 169) : 0;
        pfv[k]   = pfv[k] && (pfil[k] < nimg);
        pf[k] = pfv[k] ? g_act2[((b0 + pfil[k]) * 64 + 0) * 169 + pfidx[k]] : 0.f;
    }

#pragma unroll 1
    for (int c = 0; c < 64; c++) {
#pragma unroll
        for (int k = 0; k < 4; k++) {
            const int i = t + 256 * k;
            if (i < 845) {
                __nv_bfloat16 h, l;
                bf16_split(pf[k], h, l);
                ph[i] = h; pl[i] = l;
            }
        }
        __syncthreads();

        if (c + 1 < 64) {
#pragma unroll
            for (int k = 0; k < 4; k++)
                if (pfv[k])
                    pf[k] = g_act2[((b0 + pfil[k]) * 64 + (c + 1)) * 169 + pfidx[k]];
        }

        if (t < 125) {
            const int il = t / 25, p = t % 25;
            if (il < nimg) {
                const int oy = p / 5, ox = p % 5;
                const int ib = il * 169 + oy * 26 + ox * 2;
                const int rb = t * 40;
#pragma unroll
                for (int j2 = 0; j2 < 13; j2++) {
                    const int k0 = 2 * j2;
                    const int o0 = (k0 / 5) * 13 + (k0 % 5);
                    __nv_bfloat16 h0 = ph[ib + o0], l0 = pl[ib + o0];
                    __nv_bfloat16 h1, l1;
                    if (k0 + 1 < 25) {
                        const int o1 = ((k0 + 1) / 5) * 13 + ((k0 + 1) % 5);
                        h1 = ph[ib + o1]; l1 = pl[ib + o1];
                    } else {
                        h1 = __ushort_as_bfloat16(0); l1 = __ushort_as_bfloat16(0);
                    }
                    *reinterpret_cast<uint32_t*>(&Ah[rb + k0]) = pack2(h0, h1);
                    *reinterpret_cast<uint32_t*>(&Al[rb + k0]) = pack2(l0, l1);
                }
            }
        } else if (t < 253) {
            const int oc = t - 125;
            const float* ws = w3 + oc * 1600 + c * 25;
            const int rb = oc * 40;
#pragma unroll
            for (int j2 = 0; j2 < 13; j2++) {
                const int k0 = 2 * j2;
                float v0 = ws[k0];
                float v1 = (k0 + 1 < 25) ? ws[k0 + 1] : 0.f;
                __nv_bfloat16 h0, l0, h1, l1;
                bf16_split(v0, h0, l0);
                bf16_split(v1, h1, l1);
                *reinterpret_cast<uint32_t*>(&Bh[rb + k0]) = pack2(h0, h1);
                *reinterpret_cast<uint32_t*>(&Bl[rb + k0]) = pack2(l0, l1);
            }
        }
        __syncthreads();

#pragma unroll
        for (int ks = 0; ks < 2; ks++) {
            const int kc = ks * 16;
            uint32_t a[4][4], bh[4][2], bl[4][2];
#pragma unroll
            for (int mt = 0; mt < 4; mt++) {
                const int r = wm * 64 + mt * 16;
                a[mt][0] = *reinterpret_cast<uint32_t*>(&Ah[(r + g) * 40 + kc + 2 * tq]);
                a[mt][1] = *reinterpret_cast<uint32_t*>(&Ah[(r + g + 8) * 40 + kc + 2 * tq]);
                a[mt][2] = *reinterpret_cast<uint32_t*>(&Ah[(r + g) * 40 + kc + 2 * tq + 8]);
                a[mt][3] = *reinterpret_cast<uint32_t*>(&Ah[(r + g + 8) * 40 + kc + 2 * tq + 8]);
            }
#pragma unroll
            for (int nt = 0; nt < 4; nt++) {
                const int n = wn * 32 + nt * 8 + g;
                bh[nt][0] = *reinterpret_cast<uint32_t*>(&Bh[n * 40 + kc + 2 * tq]);
                bh[nt][1] = *reinterpret_cast<uint32_t*>(&Bh[n * 40 + kc + 2 * tq + 8]);
                bl[nt][0] = *reinterpret_cast<uint32_t*>(&Bl[n * 40 + kc + 2 * tq]);
                bl[nt][1] = *reinterpret_cast<uint32_t*>(&Bl[n * 40 + kc + 2 * tq + 8]);
            }
#pragma unroll
            for (int mt = 0; mt < 4; mt++)
#pragma unroll
                for (int nt = 0; nt < 4; nt++) {
                    mma16816(acc[mt][nt], a[mt], bh[nt]);
                    mma16816(acc[mt][nt], a[mt], bl[nt]);
                }
#pragma unroll
            for (int mt = 0; mt < 4; mt++) {
                const int r = wm * 64 + mt * 16;
                a[mt][0] = *reinterpret_cast<uint32_t*>(&Al[(r + g) * 40 + kc + 2 * tq]);
                a[mt][1] = *reinterpret_cast<uint32_t*>(&Al[(r + g + 8) * 40 + kc + 2 * tq]);
                a[mt][2] = *reinterpret_cast<uint32_t*>(&Al[(r + g) * 40 + kc + 2 * tq + 8]);
                a[mt][3] = *reinterpret_cast<uint32_t*>(&Al[(r + g + 8) * 40 + kc + 2 * tq + 8]);
            }
#pragma unroll
            for (int mt = 0; mt < 4; mt++)
#pragma unroll
                for (int nt = 0; nt < 4; nt++)
                    mma16816(acc[mt][nt], a[mt], bh[nt]);
        }
        __syncthreads();
    }

#pragma unroll
    for (int mt = 0; mt < 4; mt++) {
#pragma unroll
        for (int nt = 0; nt < 4; nt++) {
            const int n0 = wn * 32 + nt * 8 + 2 * tq;
            const float bi0 = b3[n0], bi1 = b3[n0 + 1];
#pragma unroll
            for (int half = 0; half < 2; half++) {
                const int r = wm * 64 + mt * 16 + g + half * 8;
                if (r < 125) {
                    const int il = r / 25, p = r % 25;
                    if (il < nimg) {
                        float* o = g_act3 + ((b0 + il) * 128) * 25 + p;
                        o[n0 * 25]       = fmaxf(acc[mt][nt][half * 2 + 0] + bi0, 0.f);
                        o[(n0 + 1) * 25] = fmaxf(acc[mt][nt][half * 2 + 1] + bi1, 0.f);
                    }
                }
            }
        }
    }
}

// ============================================================================
// conv4: split-K x10 scalar GEMM partials. grid (16,4,10), chunk 320.
// ============================================================================
__global__ __launch_bounds__(256) void conv4_kernel(
    const float* __restrict__ w4)
{
    __shared__ float s_a[32 * 68];
    __shared__ float s_w[32 * 68];

    const int bm = blockIdx.x * 64;
    const int bn = blockIdx.y * 64;
    const int kz = blockIdx.z;
    const int t  = threadIdx.x;
    const int tx = t & 15;
    const int ty = t >> 4;

    const float* A = g_act3;

    float acc[4][4];
#pragma unroll
    for (int i = 0; i < 4; i++)
#pragma unroll
        for (int j = 0; j < 4; j++) acc[i][j] = 0.f;

#pragma unroll 1
    for (int k0 = kz * 320; k0 < kz * 320 + 320; k0 += 32) {
        __syncthreads();
        for (int e = t; e < 2048; e += 256) {
            int r = e >> 5, kk = e & 31;
            s_a[kk * 68 + r] = A[(bm + r) * 3200 + k0 + kk];
            s_w[kk * 68 + r] = w4[(bn + r) * 3200 + k0 + kk];
        }
        __syncthreads();

#pragma unroll 4
        for (int kk = 0; kk < 32; kk++) {
            float4 av = *reinterpret_cast<const float4*>(&s_a[kk * 68 + ty * 4]);
            float4 wv = *reinterpret_cast<const float4*>(&s_w[kk * 68 + tx * 4]);
            float a[4] = {av.x, av.y, av.z, av.w};
            float w[4] = {wv.x, wv.y, wv.z, wv.w};
#pragma unroll
            for (int i = 0; i < 4; i++)
#pragma unroll
                for (int j = 0; j < 4; j++) acc[i][j] += a[i] * w[j];
        }
    }

    float* dst = g_featp + kz * (BATCH * 256);
#pragma unroll
    for (int i = 0; i < 4; i++)
#pragma unroll
        for (int j = 0; j < 4; j++)
            dst[(bm + ty * 4 + i) * 256 + (bn + tx * 4 + j)] = acc[i][j];
}

// ============================================================================
// head: feat = relu(sum_z partials + b4); latent; log_alpha; stopping softmax
// ============================================================================
__global__ __launch_bounds__(256) void head_kernel(
    const float* __restrict__ b4,
    const float* __restrict__ enc_w, const float* __restrict__ enc_b,
    const float* __restrict__ sink_w, const float* __restrict__ sink_b,
    const float* __restrict__ mask_w, const float* __restrict__ mask_b,
    float* __restrict__ out_stop)
{
    __shared__ float s_encw[16 * 257];
    __shared__ float s_feat[16][256];
    __shared__ float s_sw[576], s_sb[36], s_mw[96], s_mb[6];
    __shared__ float s_lat[16][16];

    const int t  = threadIdx.x;
    const int b0 = blockIdx.x * 16;

    for (int e = t; e < 4096; e += 256) {
        int l = e >> 8, i = e & 255;
        s_encw[l * 257 + i] = enc_w[e];
        float v = b4[i];
#pragma unroll
        for (int z = 0; z < KZ4; z++)
            v += g_featp[z * (BATCH * 256) + (b0 + l) * 256 + i];
        s_feat[l][i] = fmaxf(v, 0.f);
    }
    for (int e = t; e < 576; e += 256) s_sw[e] = sink_w[e];
    if (t < 36) s_sb[t] = sink_b[t];
    for (int e = t; e < 96; e += 256) s_mw[e] = mask_w[e];
    if (t < 6) s_mb[t] = mask_b[t];
    __syncthreads();

    const int bl = t >> 4;
    const int l  = t & 15;
    const int b  = b0 + bl;

    float lat = enc_b[l];
#pragma unroll 8
    for (int i = 0; i < 256; i++)
        lat += s_feat[bl][i] * s_encw[l * 257 + i];
    s_lat[bl][l] = lat;
    __syncthreads();

    for (int rr = l; rr < 36; rr += 16) {
        float la = s_sb[rr];
#pragma unroll
        for (int i = 0; i < 16; i++) la += s_lat[bl][i] * s_sw[rr * 16 + i];
        g_logalpha[b * 36 + rr] = la;
    }

    if (l == 0) {
        float lg[6];
        float mx = -1e30f;
#pragma unroll
        for (int k = 0; k < 6; k++) {
            float v = s_mb[k];
#pragma unroll
            for (int i = 0; i < 16; i++) v += s_lat[bl][i] * s_mw[k * 16 + i];
            lg[k] = v;
            mx = fmaxf(mx, v);
        }
        float sum = 0.f;
#pragma unroll
        for (int k = 0; k < 6; k++) { lg[k] = __expf(lg[k] - mx); sum += lg[k]; }
        float inv = 1.f / sum;
#pragma unroll
        for (int k = 0; k < 6; k++) out_stop[b * 6 + k] = lg[k] * inv;
    }
}

// ============================================================================
// sinkhorn: one thread per 6x6 matrix, grid 64 x block 128 (spread over SMs)
// ============================================================================
__global__ __launch_bounds__(128) void sinkhorn_kernel(
    const float* __restrict__ gn, const float* __restrict__ seq,
    float* __restrict__ out_ordered)
{
    const int m = blockIdx.x * 128 + threadIdx.x;
    const int b = m & (BATCH - 1);

    float la[36];
#pragma unroll
    for (int i = 0; i < 36; i++)
        la[i] = g_logalpha[b * 36 + i] + gn[m * 36 + i];

    float sq[6];
#pragma unroll
    for (int j = 0; j < 6; j++) sq[j] = seq[b * 6 + j];

#pragma unroll 1
    for (int it = 0; it < NITERS; it++) {
#pragma unroll
        for (int j = 0; j < 6; j++) {
            float mx = la[j * 6];
#pragma unroll
            for (int k = 1; k < 6; k++) mx = fmaxf(mx, la[j * 6 + k]);
            float s = 0.f;
#pragma unroll
            for (int k = 0; k < 6; k++) s += __expf(la[j * 6 + k] - mx);
            float lse = mx + __logf(s);
#pragma unroll
            for (int k = 0; k < 6; k++) la[j * 6 + k] -= lse;
        }
#pragma unroll
        for (int k = 0; k < 6; k++) {
            float mx = la[k];
#pragma unroll
            for (int j = 1; j < 6; j++) mx = fmaxf(mx, la[j * 6 + k]);
            float s = 0.f;
#pragma unroll
            for (int j = 0; j < 6; j++) s += __expf(la[j * 6 + k] - mx);
            float lse = mx + __logf(s);
#pragma unroll
            for (int j = 0; j < 6; j++) la[j * 6 + k] -= lse;
        }
    }

#pragma unroll
    for (int k = 0; k < 6; k++) {
        float o = 0.f;
#pragma unroll
        for (int j = 0; j < 6; j++) o += __expf(la[j * 6 + k]) * sq[j];
        out_ordered[m * 6 + k] = o;
    }
}

// ============================================================================
extern "C" void kernel_launch(void* const* d_in, const int* in_sizes, int n_in,
                              void* d_out, int out_size)
{
    const float* seq    = (const float*)d_in[0];
    const float* im     = (const float*)d_in[1];
    const float* gn     = (const float*)d_in[2];
    const float* w1     = (const float*)d_in[3];
    const float* b1     = (const float*)d_in[4];
    const float* w2     = (const float*)d_in[5];
    const float* b2     = (const float*)d_in[6];
    const float* w3     = (const float*)d_in[7];
    const float* b3     = (const float*)d_in[8];
    const float* w4     = (const float*)d_in[9];
    const float* b4     = (const float*)d_in[10];
    const float* enc_w  = (const float*)d_in[11];
    const float* enc_b  = (const float*)d_in[12];
    const float* sink_w = (const float*)d_in[13];
    const float* sink_b = (const float*)d_in[14];
    const float* mask_w = (const float*)d_in[15];
    const float* mask_b = (const float*)d_in[16];

    float* out = (float*)d_out;
    float* out_ordered = out;                         // [8192*6]
    float* out_stop    = out + NSAMP * BATCH * KDIM;  // [1024*6]

    conv1_kernel<<<dim3(BATCH, 2), 256>>>(im, w1, b1);
    conv2_mma<<<BATCH, 256, C2_SMEM_BF16 * 2>>>(w2, b2);
    conv3_mma<<<205, 256, C3_SMEM_BF16 * 2>>>(w3, b3);
    conv4_kernel<<<dim3(16, 4, KZ4), 256>>>(w4);
    head_kernel<<<64, 256>>>(b4, enc_w, enc_b, sink_w, sink_b, mask_w, mask_b, out_stop);
    sinkhorn_kernel<<<64, 128>>>(gn, seq, out_ordered);
}